// round 13
// baseline (speedup 1.0000x reference)
#include <cuda_runtime.h>
#include <cuda_fp16.h>
#include <stdint.h>
#include <math.h>

// Problem dims (fixed)
#define B_ 256
#define S_ 256
#define I_ 3
#define H_ 1024
#define T_ 64
#define BH (B_*H_)

#define BM 64
#define BN 32
#define BK 64
#define KCH 16
#define NCTA 128
#define THREADS 256
#define GSZ 32            // CTAs per band

// Shared memory layout (halves):
//  [0, 32768)        : cached W slice A (CW0: eWhh0 / dWhh1)   64 KB
//  [32768, 65536)    : cached W slice B (CW2: eWhh1)            64 KB
//  [65536, +4*SSTR)  : 4 pipeline stages (A0 8KB, A1 8KB, WS 4KB)
#define CW0_OFF 0
#define CW2_OFF 32768
#define STG_OFF 65536
#define O_A0 0
#define O_A1 4096
#define O_WS 8192
#define SSTR 10240
#define SMEM_BYTES ((STG_OFF + 4*SSTR)*2)   // 212992 B

// ---------------------------------------------------------------------------
// Device scratch (no allocation allowed)
// ---------------------------------------------------------------------------
__device__ __half g_y0[4*BH];            // enc layer-0 output ring (4 slots)
__device__ __half g_h1[4*BH];            // enc layer-1 hidden ring (4 slots)
__device__ __half g_hA[2*BH], g_hB[2*BH];
__device__ __half g_zb[BH];
__device__ float  g_inp[2*B_*I_];        // feedback ping-pong
// 0:eWhh0 1:eWih1 2:eWhh1 3:dWhh0 4:dWih1 5:dWhh1
__device__ __half g_W[6][H_*H_];
__device__ float  g_bs[4][H_];           // summed biases: enc0, enc1, dec0, dec1
__device__ unsigned g_cA[4*32];          // enc0 per-band counters (padded)
__device__ unsigned g_cB[4*32];          // enc1 per-band counters
__device__ unsigned g_cD[4*32];          // decoder per-band counters

// ---------------------------------------------------------------------------
__global__ void k_init(const float* __restrict__ x,
                       const float* __restrict__ ebih0, const float* __restrict__ ebhh0,
                       const float* __restrict__ ebih1, const float* __restrict__ ebhh1,
                       const float* __restrict__ dbih0, const float* __restrict__ dbhh0,
                       const float* __restrict__ dbih1, const float* __restrict__ dbhh1) {
    int i = blockIdx.x * blockDim.x + threadIdx.x;
    if (i < 4) { g_cA[i*32] = 0; g_cB[i*32] = 0; g_cD[i*32] = 0; }
    if (i < BH) g_zb[i] = __float2half(0.0f);
    if (i < B_*I_) {
        int b = i / I_, c = i % I_;
        g_inp[B_*I_ + i] = x[b*(S_*I_) + (S_-1)*I_ + c];   // slot 1 = initial
    }
    if (i < H_) {
        g_bs[0][i] = ebih0[i] + ebhh0[i];
        g_bs[1][i] = ebih1[i] + ebhh1[i];
        g_bs[2][i] = dbih0[i] + dbhh0[i];
        g_bs[3][i] = dbih1[i] + dbhh1[i];
    }
}

__global__ void k_conv6(const float* __restrict__ s0, const float* __restrict__ s1,
                        const float* __restrict__ s2, const float* __restrict__ s3,
                        const float* __restrict__ s4, const float* __restrict__ s5) {
    int i = blockIdx.x * blockDim.x + threadIdx.x;
    const float* srcs[6] = {s0, s1, s2, s3, s4, s5};
    int j = blockIdx.y;
    g_W[j][i] = __float2half(srcs[j][i]);
}

// ---------------------------------------------------------------------------
// Split band sync: tid0-only arrive (atomic) / wait (poll), fences included.
// ---------------------------------------------------------------------------
__device__ __forceinline__ void arrive_cnt(unsigned* c, int tid) {
    __syncthreads();
    if (tid == 0) { __threadfence(); atomicAdd(c, 1u); }
}
__device__ __forceinline__ void wait_cnt(unsigned* c, unsigned target, int tid) {
    if (tid == 0) {
        while (*(volatile unsigned*)c < target) { }
        __threadfence();
    }
    __syncthreads();
}

__device__ __forceinline__ uint32_t smaddr(const void* p) {
    return (uint32_t)__cvta_generic_to_shared(p);
}
#define CP16(dst_sm, src_gm) \
    asm volatile("cp.async.cg.shared.global [%0], [%1], 16;\n" \
                 :: "r"(dst_sm), "l"(src_gm))
#define CPCOMMIT() asm volatile("cp.async.commit_group;")
#define CPWAIT2()  asm volatile("cp.async.wait_group 2;")

__device__ __forceinline__ float tanhA(float x) {
    float y; asm("tanh.approx.f32 %0, %1;" : "=f"(y) : "f"(x)); return y;
}

// Load this CTA's 32x1024 W slice into a smem cache region (16 chunks).
__device__ void loadWc(const __half* __restrict__ W, __half* Wc, int bn0, int tid) {
    const int lrow = tid >> 3, lcolh = (tid & 7) * 8;   // lrow 0..31
    const int sc = lcolh ^ ((lrow & 7) * 8);
    for (int kc = 0; kc < KCH; ++kc)
        CP16(smaddr(Wc + kc*2048 + lrow*64 + sc),
             W + (size_t)(bn0 + lrow)*H_ + kc*64 + lcolh);
    CPCOMMIT();
    asm volatile("cp.async.wait_group 0;");
    __syncthreads();
}

// Decoder W-stream prefetch: chunks 0..2 into stages 0..2 (3 groups).
__device__ void preW3(const __half* __restrict__ Wst, int bn0, int tid, __half* sm) {
    __half* stg = sm + STG_OFF;
    const int lrow = tid >> 3, lcolh = (tid & 7) * 8;
    const int sc = lcolh ^ ((lrow & 7) * 8);
    #pragma unroll
    for (int c = 0; c < 3; ++c) {
        CP16(smaddr(stg + c*SSTR + O_WS + lrow*64 + sc),
             Wst + (size_t)(bn0 + lrow)*H_ + c*BK + lcolh);
        CPCOMMIT();
    }
}

// ldmatrix helpers (row width 64 halves, XOR swizzle on 8-half granule)
__device__ __forceinline__ void ldaW(uint32_t a[4], const __half* base, int kh, int lane, int wm) {
    int r  = wm*16 + (lane & 15);
    int cc = (kh + ((lane >> 4) * 8)) ^ ((r & 7) * 8);
    uint32_t addr = smaddr(base + r*64 + cc);
    asm volatile("ldmatrix.sync.aligned.m8n8.x4.shared.b16 {%0,%1,%2,%3}, [%4];"
        : "=r"(a[0]), "=r"(a[1]), "=r"(a[2]), "=r"(a[3]) : "r"(addr));
}
__device__ __forceinline__ void ldbW(uint32_t b[4], const __half* base, int kh, int lane, int wn) {
    int j  = lane >> 3;
    int r  = wn*16 + ((j >> 1) * 8) + (lane & 7);
    int cc = (kh + (j & 1) * 8) ^ ((r & 7) * 8);
    uint32_t addr = smaddr(base + r*64 + cc);
    asm volatile("ldmatrix.sync.aligned.m8n8.x4.shared.b16 {%0,%1,%2,%3}, [%4];"
        : "=r"(b[0]), "=r"(b[1]), "=r"(b[2]), "=r"(b[3]) : "r"(addr));
}
__device__ __forceinline__ void mma2(float acc[2][4], const uint32_t a[4], const uint32_t b[4]) {
    #pragma unroll
    for (int ni = 0; ni < 2; ++ni)
        asm volatile(
            "mma.sync.aligned.m16n8k16.row.col.f32.f16.f16.f32 "
            "{%0,%1,%2,%3}, {%4,%5,%6,%7}, {%8,%9}, {%0,%1,%2,%3};"
            : "+f"(acc[ni][0]), "+f"(acc[ni][1]), "+f"(acc[ni][2]), "+f"(acc[ni][3])
            : "r"(a[0]), "r"(a[1]), "r"(a[2]), "r"(a[3]),
              "r"(b[2*ni]), "r"(b[2*ni+1]));
}

// Epilogue: optional x-projection + summed bias, tanh(approx), fp16 write.
template<int APPROX>
__device__ __forceinline__ void epi(
    float acc[2][4],
    const float* __restrict__ xs, int xs_stride, const float* __restrict__ Wsm,
    const float* __restrict__ bs,
    __half* __restrict__ C,
    int bm0, int bn0, int lane, int wm, int wn)
{
    #pragma unroll
    for (int h = 0; h < 2; ++h) {
        const int row = bm0 + wm*16 + (lane >> 2) + h*8;
        float x0 = 0.f, x1 = 0.f, x2 = 0.f;
        if (xs) {
            const float* xr = xs + (size_t)row * xs_stride;
            x0 = xr[0]; x1 = xr[1]; x2 = xr[2];
        }
        #pragma unroll
        for (int ni = 0; ni < 2; ++ni) {
            const int col = bn0 + wn*16 + ni*8 + (lane & 3)*2;
            float v0 = acc[ni][h*2 + 0];
            float v1 = acc[ni][h*2 + 1];
            if (xs) {
                v0 += x0*Wsm[col*3+0] + x1*Wsm[col*3+1] + x2*Wsm[col*3+2];
                v1 += x0*Wsm[(col+1)*3+0] + x1*Wsm[(col+1)*3+1] + x2*Wsm[(col+1)*3+2];
            }
            v0 += bs[col];
            v1 += bs[col+1];
            if (APPROX) { v0 = tanhA(v0); v1 = tanhA(v1); }
            else        { v0 = tanhf(v0); v1 = tanhf(v1); }
            *(__half2*)(C + (size_t)row*H_ + col) =
                __halves2half2(__float2half(v0), __float2half(v1));
        }
    }
}

// ---------------------------------------------------------------------------
// Encoder phase 0 (interval t): ys0[t] = tanh(x[t]@Wih0 + Y[t-1]@W0cached + b)
// Single product, A-only stream, W cached in CW0.
// ---------------------------------------------------------------------------
__device__ void enc0_phase(int t,
    const __half* __restrict__ Y,
    const float* __restrict__ x, const float* __restrict__ eWih0,
    __half* __restrict__ Yout,
    int bm0, int bn0, int tid, __half* sm)
{
    const int lane = tid & 31, wrp = tid >> 5, wm = wrp >> 1, wn = wrp & 1;
    const int lrow = tid >> 3, lcolh = (tid & 7) * 8;
    __half* stg = sm + STG_OFF;
    const __half* CW0 = sm + CW0_OFF;

    auto pfA = [&](int c, int slot) {
        __half* st = stg + slot*SSTR;
        const int k0 = c*BK;
        #pragma unroll
        for (int i = 0; i < 2; ++i) {
            int r  = lrow + 32*i;
            int sc = lcolh ^ ((r & 7) * 8);
            CP16(smaddr(st + O_A0 + r*64 + sc), Y + (size_t)(bm0 + r)*H_ + k0 + lcolh);
        }
    };

    pfA(0, 0); CPCOMMIT();
    pfA(1, 1); CPCOMMIT();
    pfA(2, 2); CPCOMMIT();

    float acc[2][4] = {};
    for (int c = 0; c < KCH; ++c) {
        CPWAIT2();
        __syncthreads();
        if (c + 3 < KCH) pfA(c + 3, (c + 3) & 3);
        CPCOMMIT();

        const __half* st = stg + (c & 3)*SSTR;
        #pragma unroll
        for (int k16 = 0; k16 < 4; ++k16) {
            const int kh = 16*k16;
            uint32_t a0[4], bc[4];
            ldaW(a0, st + O_A0, kh, lane, wm);
            ldbW(bc, CW0 + c*2048, kh, lane, wn);
            mma2(acc, a0, bc);
        }
    }
    epi<1>(acc, x + t*I_, S_*I_, eWih0, g_bs[0], Yout, bm0, bn0, lane, wm, wn);
}

// ---------------------------------------------------------------------------
// Encoder phase 1 (interval t): h1[t-1] = tanh(Y[t-1]@W1stream + H[t-2]@W2cached + b)
// ---------------------------------------------------------------------------
__device__ void enc1_phase(
    const __half* __restrict__ Y, const __half* __restrict__ Hp,
    __half* __restrict__ Hout,
    int bm0, int bn0, int tid, __half* sm)
{
    const int lane = tid & 31, wrp = tid >> 5, wm = wrp >> 1, wn = wrp & 1;
    const int lrow = tid >> 3, lcolh = (tid & 7) * 8;
    __half* stg = sm + STG_OFF;
    const __half* CW2 = sm + CW2_OFF;

    auto pf = [&](int c, int slot) {
        __half* st = stg + slot*SSTR;
        const int k0 = c*BK;
        #pragma unroll
        for (int i = 0; i < 2; ++i) {
            int r  = lrow + 32*i;
            int sc = lcolh ^ ((r & 7) * 8);
            CP16(smaddr(st + O_A0 + r*64 + sc), Y  + (size_t)(bm0 + r)*H_ + k0 + lcolh);
            CP16(smaddr(st + O_A1 + r*64 + sc), Hp + (size_t)(bm0 + r)*H_ + k0 + lcolh);
        }
        int sc2 = lcolh ^ ((lrow & 7) * 8);
        CP16(smaddr(st + O_WS + lrow*64 + sc2), g_W[1] + (size_t)(bn0 + lrow)*H_ + k0 + lcolh);
    };

    pf(0, 0); CPCOMMIT();
    pf(1, 1); CPCOMMIT();
    pf(2, 2); CPCOMMIT();

    float acc[2][4] = {};
    for (int c = 0; c < KCH; ++c) {
        CPWAIT2();
        __syncthreads();
        if (c + 3 < KCH) pf(c + 3, (c + 3) & 3);
        CPCOMMIT();

        const __half* st = stg + (c & 3)*SSTR;
        #pragma unroll
        for (int k16 = 0; k16 < 4; ++k16) {
            const int kh = 16*k16;
            uint32_t ay[4], bs_[4];
            ldaW(ay, st + O_A0, kh, lane, wm);
            ldbW(bs_, st + O_WS, kh, lane, wn);
            mma2(acc, ay, bs_);
            uint32_t ah[4], bc[4];
            ldaW(ah, st + O_A1, kh, lane, wm);
            ldbW(bc, CW2 + c*2048, kh, lane, wn);
            mma2(acc, ah, bc);
        }
    }
    epi<1>(acc, nullptr, 0, nullptr, g_bs[1], Hout, bm0, bn0, lane, wm, wn);
}

// ---------------------------------------------------------------------------
// Decoder layer-0 interval (W3=dWhh0 streamed; entry: W3 chunks 0..2 staged):
//   hA = tanh(A0@W3 + inp@dWih0 + b); inp computed on the fly from out[:,t-1].
// ---------------------------------------------------------------------------
template<int FB>
__device__ void dec0(
    const __half* __restrict__ A0,
    const float* __restrict__ dWih0,
    const float* __restrict__ inp_prev, float* __restrict__ inp_cur,
    float* __restrict__ out, int t, const float* __restrict__ dblin,
    __half* __restrict__ Cout,
    int bm0, int bn0, int tid, __half* sm)
{
    const int lane = tid & 31, wrp = tid >> 5, wm = wrp >> 1, wn = wrp & 1;
    const int lrow = tid >> 3, lcolh = (tid & 7) * 8;
    __half* stg = sm + STG_OFF;

    auto pfA = [&](int c, int slot) {
        __half* st = stg + slot*SSTR;
        const int k0 = c*BK;
        #pragma unroll
        for (int i = 0; i < 2; ++i) {
            int r  = lrow + 32*i;
            int sc = lcolh ^ ((r & 7) * 8);
            CP16(smaddr(st + O_A0 + r*64 + sc), A0 + (size_t)(bm0 + r)*H_ + k0 + lcolh);
        }
    };
    auto pfW = [&](int c, int slot) {
        __half* st = stg + slot*SSTR;
        const int k0 = c*BK;
        int sc = lcolh ^ ((lrow & 7) * 8);
        CP16(smaddr(st + O_WS + lrow*64 + sc), g_W[3] + (size_t)(bn0 + lrow)*H_ + k0 + lcolh);
    };

    pfA(0, 0); CPCOMMIT();
    pfA(1, 1); CPCOMMIT();
    pfA(2, 2); CPCOMMIT();

    float acc[2][4] = {};
    for (int c = 0; c < KCH; ++c) {
        CPWAIT2();
        __syncthreads();
        if (c + 3 < KCH) { pfW(c + 3, (c + 3) & 3); pfA(c + 3, (c + 3) & 3); }
        CPCOMMIT();

        const __half* st = stg + (c & 3)*SSTR;
        #pragma unroll
        for (int k16 = 0; k16 < 4; ++k16) {
            const int kh = 16*k16;
            uint32_t a0[4], bA[4];
            ldaW(a0, st + O_A0, kh, lane, wm);
            ldbW(bA, st + O_WS, kh, lane, wn);
            mma2(acc, a0, bA);
        }
    }

    // Epilogue with on-the-fly feedback.
    #pragma unroll
    for (int h = 0; h < 2; ++h) {
        const int row = bm0 + wm*16 + (lane >> 2) + h*8;
        float c0, c1, c2;
        if (FB) {
            c0 = out[row*T_ + (t-1)];
            const float i0 = inp_prev[row*3 + 0];
            const float i1 = inp_prev[row*3 + 1];
            c1 = i0 - c0;
            c2 = i1 - c1;
        } else {
            c0 = inp_prev[row*3 + 0];
            c1 = inp_prev[row*3 + 1];
            c2 = inp_prev[row*3 + 2];
        }
        #pragma unroll
        for (int ni = 0; ni < 2; ++ni) {
            const int col = bn0 + wn*16 + ni*8 + (lane & 3)*2;
            float v0 = acc[ni][h*2 + 0];
            float v1 = acc[ni][h*2 + 1];
            v0 += c0*dWih0[col*3+0] + c1*dWih0[col*3+1] + c2*dWih0[col*3+2];
            v1 += c0*dWih0[(col+1)*3+0] + c1*dWih0[(col+1)*3+1] + c2*dWih0[(col+1)*3+2];
            v0 += g_bs[2][col];
            v1 += g_bs[2][col+1];
            v0 = tanhA(v0); v1 = tanhA(v1);
            *(__half2*)(Cout + (size_t)row*H_ + col) =
                __halves2half2(__float2half(v0), __float2half(v1));
        }
        if (bn0 == 0 && wn == 0 && (lane & 3) == 0) {
            inp_cur[row*3 + 0] = c0;
            inp_cur[row*3 + 1] = c1;
            inp_cur[row*3 + 2] = c2;
            out[row*T_ + t] = dblin[0];   // init for dec1's atomic partial dots
        }
    }
}

// ---------------------------------------------------------------------------
// Decoder layer-1 interval (W4=dWih1 streamed, W5=dWhh1 cached in CW0):
//   hB = tanh(A0@W4 + A1@W5c + b); fused decout: atomicAdd partial hB.Wlin.
// ---------------------------------------------------------------------------
__device__ void dec1(
    const __half* __restrict__ A0, const __half* __restrict__ A1,
    const float* __restrict__ Wlin,
    float* __restrict__ out, int t,
    __half* __restrict__ Cout,
    int bm0, int bn0, int tid, __half* sm)
{
    const int lane = tid & 31, wrp = tid >> 5, wm = wrp >> 1, wn = wrp & 1;
    const int lrow = tid >> 3, lcolh = (tid & 7) * 8;
    __half* stg = sm + STG_OFF;
    const __half* CW0 = sm + CW0_OFF;

    auto pfA = [&](int c, int slot) {
        __half* st = stg + slot*SSTR;
        const int k0 = c*BK;
        #pragma unroll
        for (int i = 0; i < 2; ++i) {
            int r  = lrow + 32*i;
            int sc = lcolh ^ ((r & 7) * 8);
            CP16(smaddr(st + O_A0 + r*64 + sc), A0 + (size_t)(bm0 + r)*H_ + k0 + lcolh);
            CP16(smaddr(st + O_A1 + r*64 + sc), A1 + (size_t)(bm0 + r)*H_ + k0 + lcolh);
        }
    };
    auto pfW = [&](int c, int slot) {
        __half* st = stg + slot*SSTR;
        const int k0 = c*BK;
        int sc = lcolh ^ ((lrow & 7) * 8);
        CP16(smaddr(st + O_WS + lrow*64 + sc), g_W[4] + (size_t)(bn0 + lrow)*H_ + k0 + lcolh);
    };

    pfA(0, 0); CPCOMMIT();
    pfA(1, 1); CPCOMMIT();
    pfA(2, 2); CPCOMMIT();

    float acc[2][4] = {};
    for (int c = 0; c < KCH; ++c) {
        CPWAIT2();
        __syncthreads();
        if (c + 3 < KCH) { pfW(c + 3, (c + 3) & 3); pfA(c + 3, (c + 3) & 3); }
        CPCOMMIT();

        const __half* st = stg + (c & 3)*SSTR;
        #pragma unroll
        for (int k16 = 0; k16 < 4; ++k16) {
            const int kh = 16*k16;
            uint32_t a0[4], bA[4];
            ldaW(a0, st + O_A0, kh, lane, wm);
            ldbW(bA, st + O_WS, kh, lane, wn);
            mma2(acc, a0, bA);
            uint32_t a1[4], bc[4];
            ldaW(a1, st + O_A1, kh, lane, wm);
            ldbW(bc, CW0 + c*2048, kh, lane, wn);
            mma2(acc, a1, bc);
        }
    }

    // Epilogue + fused decout partial dot (exact tanhf — feeds output directly).
    #pragma unroll
    for (int h = 0; h < 2; ++h) {
        const int row = bm0 + wm*16 + (lane >> 2) + h*8;
        float s = 0.0f;
        #pragma unroll
        for (int ni = 0; ni < 2; ++ni) {
            const int col = bn0 + wn*16 + ni*8 + (lane & 3)*2;
            float v0 = acc[ni][h*2 + 0] + g_bs[3][col];
            float v1 = acc[ni][h*2 + 1] + g_bs[3][col+1];
            v0 = tanhf(v0); v1 = tanhf(v1);
            *(__half2*)(Cout + (size_t)row*H_ + col) =
                __halves2half2(__float2half(v0), __float2half(v1));
            s += v0*Wlin[col] + v1*Wlin[col+1];
        }
        s += __shfl_xor_sync(0xffffffffu, s, 1);
        s += __shfl_xor_sync(0xffffffffu, s, 2);
        if ((lane & 3) == 0)
            atomicAdd(&out[row*T_ + t], s);
    }
}

// ---------------------------------------------------------------------------
// Persistent whole-network kernel. 128 CTAs x 256 threads, 1 CTA/SM.
// ---------------------------------------------------------------------------
__global__ __launch_bounds__(256) void k_persist(
    const float* __restrict__ x,
    const float* __restrict__ eWih0,
    const float* __restrict__ dWih0,
    const float* __restrict__ dWlin, const float* __restrict__ dblin,
    float* __restrict__ out)
{
    extern __shared__ __half sm[];
    const int tid = threadIdx.x;
    const int bid = blockIdx.x;
    const int bn0 = (bid & 31) * BN;
    const int bm0 = (bid >> 5) * BM;
    const int grp = bid >> 5;
    const int lane = tid & 31, wrp = tid >> 5, wm = wrp >> 1, wn = wrp & 1;
    unsigned* cA = &g_cA[grp*32];
    unsigned* cB = &g_cB[grp*32];
    unsigned* cD = &g_cD[grp*32];
    unsigned nb = 0;

    // Cache W0 (eWhh0) and W2 (eWhh1) slices for the encoder phase.
    loadWc(g_W[0], sm + CW0_OFF, bn0, tid);
    loadWc(g_W[2], sm + CW2_OFF, bn0, tid);

    // t=0: ys0[0] = tanh(x[0]@Wih0 + b) — epilogue only (Y = 0).
    {
        float z[2][4] = {};
        epi<1>(z, x, S_*I_, eWih0, g_bs[0], g_y0 /*slot 0*/, bm0, bn0, lane, wm, wn);
    }
    arrive_cnt(cA, tid);
    wait_cnt(cA, GSZ, tid);                       // Y[0] complete band-wide

    // ---- Split-phase encoder: t = 1..255 ----
    for (int t = 1; t < S_; ++t) {
        const __half* Y  = g_y0 + (size_t)((t-1)&3)*BH;
        // Phase 0: ys0[t]
        enc0_phase(t, Y, x, eWih0, g_y0 + (size_t)(t&3)*BH, bm0, bn0, tid, sm);
        arrive_cnt(cA, tid);

        // Phase 1: h1[t-1] (gate: band enc1 done through interval t-1)
        if (t >= 2) wait_cnt(cB, GSZ*(unsigned)(t-1), tid);
        const __half* Hp = (t >= 2) ? g_h1 + (size_t)((t-2)&3)*BH : g_zb;
        enc1_phase(Y, Hp, g_h1 + (size_t)((t-1)&3)*BH, bm0, bn0, tid, sm);
        arrive_cnt(cB, tid);

        // Gate for next interval: Y[t] complete band-wide.
        wait_cnt(cA, GSZ*(unsigned)(t+1), tid);
    }
    // Tail: h1[255] (needs H[254]: band enc1 through interval 255).
    wait_cnt(cB, GSZ*(unsigned)(S_-1), tid);
    enc1_phase(g_y0 + (size_t)((S_-1)&3)*BH, g_h1 + (size_t)((S_-2)&3)*BH,
               g_h1 + (size_t)((S_-1)&3)*BH, bm0, bn0, tid, sm);
    arrive_cnt(cB, tid);
    wait_cnt(cB, GSZ*(unsigned)S_, tid);          // whole band encoder done

    // Swap CW0 cache to W5 (dWhh1); prefetch W3 stream for dec0.
    loadWc(g_W[5], sm + CW0_OFF, bn0, tid);
    preW3(g_W[3], bn0, tid, sm);

    // ---- Decoder: 2 counting-barrier intervals per step ----
    const __half* pA = g_y0 + (size_t)((S_-1)&3)*BH;   // h_enc0
    const __half* pB = g_h1 + (size_t)((S_-1)&3)*BH;   // h_enc1
    for (int t = 0; t < T_; ++t) {
        __half* nA = g_hA + (size_t)(t&1)*BH;
        const float* inp_prev = g_inp + (size_t)((t-1)&1)*B_*I_;
        float* inp_cur = g_inp + (size_t)(t&1)*B_*I_;
        if (t == 0)
            dec0<0>(pA, dWih0, inp_prev, inp_cur, out, t, dblin, nA, bm0, bn0, tid, sm);
        else
            dec0<1>(pA, dWih0, inp_prev, inp_cur, out, t, dblin, nA, bm0, bn0, tid, sm);
        arrive_cnt(cD, tid);
        preW3(g_W[4], bn0, tid, sm);
        wait_cnt(cD, GSZ * (++nb), tid);

        __half* nB = g_hB + (size_t)(t&1)*BH;
        dec1(nA, pB, dWlin, out, t, nB, bm0, bn0, tid, sm);
        arrive_cnt(cD, tid);
        if (t + 1 < T_) preW3(g_W[3], bn0, tid, sm);
        wait_cnt(cD, GSZ * (++nb), tid);

        pA = nA; pB = nB;
    }
}

// ---------------------------------------------------------------------------
// Orchestration: 3 launches on default stream (graph-capturable).
// ---------------------------------------------------------------------------
extern "C" void kernel_launch(void* const* d_in, const int* in_sizes, int n_in,
                              void* d_out, int out_size)
{
    (void)in_sizes; (void)n_in; (void)out_size;
    const float* x     = (const float*)d_in[0];
    const float* eWih0 = (const float*)d_in[2];
    const float* eWhh0 = (const float*)d_in[3];
    const float* ebih0 = (const float*)d_in[4];
    const float* ebhh0 = (const float*)d_in[5];
    const float* eWih1 = (const float*)d_in[6];
    const float* eWhh1 = (const float*)d_in[7];
    const float* ebih1 = (const float*)d_in[8];
    const float* ebhh1 = (const float*)d_in[9];
    const float* dWih0 = (const float*)d_in[10];
    const float* dWhh0 = (const float*)d_in[11];
    const float* dbih0 = (const float*)d_in[12];
    const float* dbhh0 = (const float*)d_in[13];
    const float* dWih1 = (const float*)d_in[14];
    const float* dWhh1 = (const float*)d_in[15];
    const float* dbih1 = (const float*)d_in[16];
    const float* dbhh1 = (const float*)d_in[17];
    const float* dWlin = (const float*)d_in[18];
    const float* dblin = (const float*)d_in[19];
    float* out = (float*)d_out;

    static bool s_attr = false;
    if (!s_attr) {
        cudaFuncSetAttribute(k_persist,
                             cudaFuncAttributeMaxDynamicSharedMemorySize, SMEM_BYTES);
        s_attr = true;
    }

    k_init<<<(BH + 255)/256, 256>>>(x, ebih0, ebhh0, ebih1, ebhh1,
                                    dbih0, dbhh0, dbih1, dbhh1);
    // order: eWhh0, eWih1, eWhh1, dWhh0, dWih1, dWhh1
    k_conv6<<<dim3(H_*H_/256, 6), 256>>>(eWhh0, eWih1, eWhh1, dWhh0, dWih1, dWhh1);
    k_persist<<<NCTA, THREADS, SMEM_BYTES>>>(x, eWih0, dWih0, dWlin, dblin, out);
}

// round 14
// speedup vs baseline: 1.2030x; 1.2030x over previous
#include <cuda_runtime.h>
#include <cuda_fp16.h>
#include <stdint.h>
#include <math.h>

// Problem dims (fixed)
#define B_ 256
#define S_ 256
#define I_ 3
#define H_ 1024
#define T_ 64
#define BH (B_*H_)

#define BM 64
#define BN 32
#define BK 64
#define KCH 16
#define NCTA 128
#define THREADS 256
#define GSZ 32            // CTAs per band
#define NSTG 6

// Shared memory layout (halves):
//  [0, 32768)        : cached W slice (CW0: eWhh0 / dWhh1)  64 KB
//  [32768, +6*SSTR)  : 6 pipeline stages (A0 8K, A1 8K, WA 4K, WB 4K)
#define CW0_OFF 0
#define STG_OFF 32768
#define O_A0 0
#define O_A1 4096
#define O_WA 8192
#define O_WB 10240
#define SSTR 12288
#define SMEM_BYTES ((STG_OFF + NSTG*SSTR)*2)   // 212992 B

// ---------------------------------------------------------------------------
// Device scratch (no allocation allowed)
// ---------------------------------------------------------------------------
__device__ __half g_y0[4*BH];            // enc layer-0 output ring (4 slots)
__device__ __half g_h1[4*BH];            // enc layer-1 hidden ring (4 slots)
__device__ __half g_hA[2*BH], g_hB[2*BH];
__device__ __half g_zb[BH];
__device__ float  g_inp[2*B_*I_];        // feedback ping-pong
// 0:eWhh0 1:eWih1 2:eWhh1 3:dWhh0 4:dWih1 5:dWhh1
__device__ __half g_W[6][H_*H_];
__device__ float  g_bs[4][H_];           // summed biases: enc0, enc1, dec0, dec1
__device__ unsigned g_cnt[4*32];         // per-band counters, padded

// ---------------------------------------------------------------------------
__global__ void k_init(const float* __restrict__ x,
                       const float* __restrict__ ebih0, const float* __restrict__ ebhh0,
                       const float* __restrict__ ebih1, const float* __restrict__ ebhh1,
                       const float* __restrict__ dbih0, const float* __restrict__ dbhh0,
                       const float* __restrict__ dbih1, const float* __restrict__ dbhh1) {
    int i = blockIdx.x * blockDim.x + threadIdx.x;
    if (i < 4) g_cnt[i*32] = 0;
    if (i < BH) g_zb[i] = __float2half(0.0f);
    if (i < B_*I_) {
        int b = i / I_, c = i % I_;
        g_inp[B_*I_ + i] = x[b*(S_*I_) + (S_-1)*I_ + c];   // slot 1 = initial
    }
    if (i < H_) {
        g_bs[0][i] = ebih0[i] + ebhh0[i];
        g_bs[1][i] = ebih1[i] + ebhh1[i];
        g_bs[2][i] = dbih0[i] + dbhh0[i];
        g_bs[3][i] = dbih1[i] + dbhh1[i];
    }
}

__global__ void k_conv6(const float* __restrict__ s0, const float* __restrict__ s1,
                        const float* __restrict__ s2, const float* __restrict__ s3,
                        const float* __restrict__ s4, const float* __restrict__ s5) {
    int i = blockIdx.x * blockDim.x + threadIdx.x;
    const float* srcs[6] = {s0, s1, s2, s3, s4, s5};
    int j = blockIdx.y;
    g_W[j][i] = __float2half(srcs[j][i]);
}

// ---------------------------------------------------------------------------
// Per-band (32-CTA) split barrier: monotonic counter, arrive early/wait late.
// ---------------------------------------------------------------------------
__device__ __forceinline__ void gb_arrive(int tid, int grp) {
    __syncthreads();
    if (tid == 0) { __threadfence(); atomicAdd(&g_cnt[grp*32], 1u); }
}
__device__ __forceinline__ void gb_wait(int tid, int grp, unsigned target) {
    if (tid == 0) {
        while (*(volatile unsigned*)&g_cnt[grp*32] < target) { }
        __threadfence();
    }
    __syncthreads();
}

__device__ __forceinline__ uint32_t smaddr(const void* p) {
    return (uint32_t)__cvta_generic_to_shared(p);
}
#define CP16(dst_sm, src_gm) \
    asm volatile("cp.async.cg.shared.global [%0], [%1], 16;\n" \
                 :: "r"(dst_sm), "l"(src_gm))
#define CPCOMMIT() asm volatile("cp.async.commit_group;")
#define CPWAIT()   asm volatile("cp.async.wait_group 4;")

__device__ __forceinline__ float tanhA(float x) {
    float y; asm("tanh.approx.f32 %0, %1;" : "=f"(y) : "f"(x)); return y;
}

// Load this CTA's 32x1024 W slice into the smem cache (16 chunks).
__device__ void loadWc(const __half* __restrict__ W, __half* Wc, int bn0, int tid) {
    const int lrow = tid >> 3, lcolh = (tid & 7) * 8;   // lrow 0..31
    const int sc = lcolh ^ ((lrow & 7) * 8);
    for (int kc = 0; kc < KCH; ++kc)
        CP16(smaddr(Wc + kc*2048 + lrow*64 + sc),
             W + (size_t)(bn0 + lrow)*H_ + kc*64 + lcolh);
    CPCOMMIT();
    asm volatile("cp.async.wait_group 0;");
    __syncthreads();
}

// Pre-barrier W-stream prefetch: chunks 0..4 into stages 0..4 (5 groups).
template<int NW>
__device__ void preW5(const __half* __restrict__ WA, const __half* __restrict__ WB,
                      int bn0, int tid, __half* sm) {
    __half* stg = sm + STG_OFF;
    const int lrow = tid >> 3, lcolh = (tid & 7) * 8;
    const int sc = lcolh ^ ((lrow & 7) * 8);
    #pragma unroll
    for (int c = 0; c < 5; ++c) {
        __half* st = stg + c*SSTR;
        CP16(smaddr(st + O_WA + lrow*64 + sc), WA + (size_t)(bn0 + lrow)*H_ + c*BK + lcolh);
        if (NW == 2)
            CP16(smaddr(st + O_WB + lrow*64 + sc), WB + (size_t)(bn0 + lrow)*H_ + c*BK + lcolh);
        CPCOMMIT();
    }
}

// ldmatrix helpers (row width 64 halves, XOR swizzle on 8-half granule)
__device__ __forceinline__ void ldaW(uint32_t a[4], const __half* base, int kh, int lane, int wm) {
    int r  = wm*16 + (lane & 15);
    int cc = (kh + ((lane >> 4) * 8)) ^ ((r & 7) * 8);
    uint32_t addr = smaddr(base + r*64 + cc);
    asm volatile("ldmatrix.sync.aligned.m8n8.x4.shared.b16 {%0,%1,%2,%3}, [%4];"
        : "=r"(a[0]), "=r"(a[1]), "=r"(a[2]), "=r"(a[3]) : "r"(addr));
}
__device__ __forceinline__ void ldbW(uint32_t b[4], const __half* base, int kh, int lane, int wn) {
    int j  = lane >> 3;
    int r  = wn*16 + ((j >> 1) * 8) + (lane & 7);
    int cc = (kh + (j & 1) * 8) ^ ((r & 7) * 8);
    uint32_t addr = smaddr(base + r*64 + cc);
    asm volatile("ldmatrix.sync.aligned.m8n8.x4.shared.b16 {%0,%1,%2,%3}, [%4];"
        : "=r"(b[0]), "=r"(b[1]), "=r"(b[2]), "=r"(b[3]) : "r"(addr));
}
__device__ __forceinline__ void mma2(float acc[2][4], const uint32_t a[4], const uint32_t b[4]) {
    #pragma unroll
    for (int ni = 0; ni < 2; ++ni)
        asm volatile(
            "mma.sync.aligned.m16n8k16.row.col.f32.f16.f16.f32 "
            "{%0,%1,%2,%3}, {%4,%5,%6,%7}, {%8,%9}, {%0,%1,%2,%3};"
            : "+f"(acc[ni][0]), "+f"(acc[ni][1]), "+f"(acc[ni][2]), "+f"(acc[ni][3])
            : "r"(a[0]), "r"(a[1]), "r"(a[2]), "r"(a[3]),
              "r"(b[2*ni]), "r"(b[2*ni+1]));
}

// Epilogue: optional x-projection + summed bias, tanh(approx), fp16 write.
template<int APPROX>
__device__ __forceinline__ void epi(
    float acc[2][4],
    const float* __restrict__ xs, int xs_stride, const float* __restrict__ Wsm,
    const float* __restrict__ bs,
    __half* __restrict__ C,
    int bm0, int bn0, int lane, int wm, int wn)
{
    #pragma unroll
    for (int h = 0; h < 2; ++h) {
        const int row = bm0 + wm*16 + (lane >> 2) + h*8;
        float x0 = 0.f, x1 = 0.f, x2 = 0.f;
        if (xs) {
            const float* xr = xs + (size_t)row * xs_stride;
            x0 = xr[0]; x1 = xr[1]; x2 = xr[2];
        }
        #pragma unroll
        for (int ni = 0; ni < 2; ++ni) {
            const int col = bn0 + wn*16 + ni*8 + (lane & 3)*2;
            float v0 = acc[ni][h*2 + 0];
            float v1 = acc[ni][h*2 + 1];
            if (xs) {
                v0 += x0*Wsm[col*3+0] + x1*Wsm[col*3+1] + x2*Wsm[col*3+2];
                v1 += x0*Wsm[(col+1)*3+0] + x1*Wsm[(col+1)*3+1] + x2*Wsm[(col+1)*3+2];
            }
            v0 += bs[col];
            v1 += bs[col+1];
            if (APPROX) { v0 = tanhA(v0); v1 = tanhA(v1); }
            else        { v0 = tanhf(v0); v1 = tanhf(v1); }
            *(__half2*)(C + (size_t)row*H_ + col) =
                __halves2half2(__float2half(v0), __float2half(v1));
        }
    }
}

// ---------------------------------------------------------------------------
// Fused encoder interval t (entry: W1/W2 chunks 0..4 pre-issued in stages 0..4):
//   ENC0: ys0[t]  = tanh(x[t]@Wih0 + Y@W0cached + b)        (acc0)
//   always: h1[.] = tanh(Y@W1stream + H@W2stream + b)       (acc1)
// ---------------------------------------------------------------------------
template<int ENC0>
__device__ void enc_step(int t,
    const __half* __restrict__ Y, const __half* __restrict__ Hp,
    const float* __restrict__ x, const float* __restrict__ eWih0,
    __half* __restrict__ Yout, __half* __restrict__ Hout,
    int bm0, int bn0, int tid, __half* sm)
{
    const int lane = tid & 31, wrp = tid >> 5, wm = wrp >> 1, wn = wrp & 1;
    const int lrow = tid >> 3, lcolh = (tid & 7) * 8;
    __half* stg = sm + STG_OFF;
    const __half* CW0 = sm + CW0_OFF;

    auto pfA = [&](int c, int slot) {
        __half* st = stg + slot*SSTR;
        const int k0 = c*BK;
        #pragma unroll
        for (int i = 0; i < 2; ++i) {
            int r  = lrow + 32*i;
            int sc = lcolh ^ ((r & 7) * 8);
            CP16(smaddr(st + O_A0 + r*64 + sc), Y  + (size_t)(bm0 + r)*H_ + k0 + lcolh);
            CP16(smaddr(st + O_A1 + r*64 + sc), Hp + (size_t)(bm0 + r)*H_ + k0 + lcolh);
        }
    };
    auto pfW = [&](int c, int slot) {
        __half* st = stg + slot*SSTR;
        const int k0 = c*BK;
        int sc = lcolh ^ ((lrow & 7) * 8);
        CP16(smaddr(st + O_WA + lrow*64 + sc), g_W[1] + (size_t)(bn0 + lrow)*H_ + k0 + lcolh);
        CP16(smaddr(st + O_WB + lrow*64 + sc), g_W[2] + (size_t)(bn0 + lrow)*H_ + k0 + lcolh);
    };

    // A fill: chunks 0..4 (W already pre-issued during the barrier window).
    #pragma unroll
    for (int cf = 0; cf < 5; ++cf) { pfA(cf, cf); CPCOMMIT(); }

    float acc0[2][4] = {}, acc1[2][4] = {};
    for (int c = 0; c < KCH; ++c) {
        CPWAIT();
        __syncthreads();
        if (c + 5 < KCH) { pfW(c + 5, (c + 5) % NSTG); pfA(c + 5, (c + 5) % NSTG); }
        CPCOMMIT();

        const __half* st = stg + (c % NSTG)*SSTR;
        #pragma unroll
        for (int k16 = 0; k16 < 4; ++k16) {
            const int kh = 16*k16;
            uint32_t ay[4];
            ldaW(ay, st + O_A0, kh, lane, wm);
            if (ENC0) {
                uint32_t bc[4];
                ldbW(bc, CW0 + c*2048, kh, lane, wn);
                mma2(acc0, ay, bc);
            }
            uint32_t b1w[4];
            ldbW(b1w, st + O_WA, kh, lane, wn);
            mma2(acc1, ay, b1w);
            uint32_t ah[4], b2w[4];
            ldaW(ah, st + O_A1, kh, lane, wm);
            ldbW(b2w, st + O_WB, kh, lane, wn);
            mma2(acc1, ah, b2w);
        }
    }

    if (ENC0)
        epi<1>(acc0, x + t*I_, S_*I_, eWih0, g_bs[0], Yout, bm0, bn0, lane, wm, wn);
    epi<1>(acc1, nullptr, 0, nullptr, g_bs[1], Hout, bm0, bn0, lane, wm, wn);
}

// ---------------------------------------------------------------------------
// Decoder layer-0 interval (W3=dWhh0 streamed; entry: W3 chunks 0..4 staged):
//   hA = tanh(A0@W3 + inp@dWih0 + b); inp computed on the fly from out[:,t-1].
// ---------------------------------------------------------------------------
template<int FB>
__device__ void dec0(
    const __half* __restrict__ A0,
    const float* __restrict__ dWih0,
    const float* __restrict__ inp_prev, float* __restrict__ inp_cur,
    float* __restrict__ out, int t, const float* __restrict__ dblin,
    __half* __restrict__ Cout,
    int bm0, int bn0, int tid, __half* sm)
{
    const int lane = tid & 31, wrp = tid >> 5, wm = wrp >> 1, wn = wrp & 1;
    const int lrow = tid >> 3, lcolh = (tid & 7) * 8;
    __half* stg = sm + STG_OFF;

    auto pfA = [&](int c, int slot) {
        __half* st = stg + slot*SSTR;
        const int k0 = c*BK;
        #pragma unroll
        for (int i = 0; i < 2; ++i) {
            int r  = lrow + 32*i;
            int sc = lcolh ^ ((r & 7) * 8);
            CP16(smaddr(st + O_A0 + r*64 + sc), A0 + (size_t)(bm0 + r)*H_ + k0 + lcolh);
        }
    };
    auto pfW = [&](int c, int slot) {
        __half* st = stg + slot*SSTR;
        const int k0 = c*BK;
        int sc = lcolh ^ ((lrow & 7) * 8);
        CP16(smaddr(st + O_WA + lrow*64 + sc), g_W[3] + (size_t)(bn0 + lrow)*H_ + k0 + lcolh);
    };

    #pragma unroll
    for (int cf = 0; cf < 5; ++cf) { pfA(cf, cf); CPCOMMIT(); }

    float acc[2][4] = {};
    for (int c = 0; c < KCH; ++c) {
        CPWAIT();
        __syncthreads();
        if (c + 5 < KCH) { pfW(c + 5, (c + 5) % NSTG); pfA(c + 5, (c + 5) % NSTG); }
        CPCOMMIT();

        const __half* st = stg + (c % NSTG)*SSTR;
        #pragma unroll
        for (int k16 = 0; k16 < 4; ++k16) {
            const int kh = 16*k16;
            uint32_t a0[4], bA[4];
            ldaW(a0, st + O_A0, kh, lane, wm);
            ldbW(bA, st + O_WA, kh, lane, wn);
            mma2(acc, a0, bA);
        }
    }

    // Epilogue with on-the-fly feedback.
    #pragma unroll
    for (int h = 0; h < 2; ++h) {
        const int row = bm0 + wm*16 + (lane >> 2) + h*8;
        float c0, c1, c2;
        if (FB) {
            c0 = out[row*T_ + (t-1)];
            const float i0 = inp_prev[row*3 + 0];
            const float i1 = inp_prev[row*3 + 1];
            c1 = i0 - c0;
            c2 = i1 - c1;
        } else {
            c0 = inp_prev[row*3 + 0];
            c1 = inp_prev[row*3 + 1];
            c2 = inp_prev[row*3 + 2];
        }
        #pragma unroll
        for (int ni = 0; ni < 2; ++ni) {
            const int col = bn0 + wn*16 + ni*8 + (lane & 3)*2;
            float v0 = acc[ni][h*2 + 0];
            float v1 = acc[ni][h*2 + 1];
            v0 += c0*dWih0[col*3+0] + c1*dWih0[col*3+1] + c2*dWih0[col*3+2];
            v1 += c0*dWih0[(col+1)*3+0] + c1*dWih0[(col+1)*3+1] + c2*dWih0[(col+1)*3+2];
            v0 += g_bs[2][col];
            v1 += g_bs[2][col+1];
            v0 = tanhA(v0); v1 = tanhA(v1);
            *(__half2*)(Cout + (size_t)row*H_ + col) =
                __halves2half2(__float2half(v0), __float2half(v1));
        }
        if (bn0 == 0 && wn == 0 && (lane & 3) == 0) {
            inp_cur[row*3 + 0] = c0;
            inp_cur[row*3 + 1] = c1;
            inp_cur[row*3 + 2] = c2;
            out[row*T_ + t] = dblin[0];   // init for dec1's atomic partial dots
        }
    }
}

// ---------------------------------------------------------------------------
// Decoder layer-1 interval (W4=dWih1 streamed, W5=dWhh1 cached in CW0):
//   hB = tanh(A0@W4 + A1@W5c + b); fused decout: atomicAdd partial hB.Wlin.
// ---------------------------------------------------------------------------
__device__ void dec1(
    const __half* __restrict__ A0, const __half* __restrict__ A1,
    const float* __restrict__ Wlin,
    float* __restrict__ out, int t,
    __half* __restrict__ Cout,
    int bm0, int bn0, int tid, __half* sm)
{
    const int lane = tid & 31, wrp = tid >> 5, wm = wrp >> 1, wn = wrp & 1;
    const int lrow = tid >> 3, lcolh = (tid & 7) * 8;
    __half* stg = sm + STG_OFF;
    const __half* CW0 = sm + CW0_OFF;

    auto pfA = [&](int c, int slot) {
        __half* st = stg + slot*SSTR;
        const int k0 = c*BK;
        #pragma unroll
        for (int i = 0; i < 2; ++i) {
            int r  = lrow + 32*i;
            int sc = lcolh ^ ((r & 7) * 8);
            CP16(smaddr(st + O_A0 + r*64 + sc), A0 + (size_t)(bm0 + r)*H_ + k0 + lcolh);
            CP16(smaddr(st + O_A1 + r*64 + sc), A1 + (size_t)(bm0 + r)*H_ + k0 + lcolh);
        }
    };
    auto pfW = [&](int c, int slot) {
        __half* st = stg + slot*SSTR;
        const int k0 = c*BK;
        int sc = lcolh ^ ((lrow & 7) * 8);
        CP16(smaddr(st + O_WA + lrow*64 + sc), g_W[4] + (size_t)(bn0 + lrow)*H_ + k0 + lcolh);
    };

    #pragma unroll
    for (int cf = 0; cf < 5; ++cf) { pfA(cf, cf); CPCOMMIT(); }

    float acc[2][4] = {};
    for (int c = 0; c < KCH; ++c) {
        CPWAIT();
        __syncthreads();
        if (c + 5 < KCH) { pfW(c + 5, (c + 5) % NSTG); pfA(c + 5, (c + 5) % NSTG); }
        CPCOMMIT();

        const __half* st = stg + (c % NSTG)*SSTR;
        #pragma unroll
        for (int k16 = 0; k16 < 4; ++k16) {
            const int kh = 16*k16;
            uint32_t a0[4], bA[4];
            ldaW(a0, st + O_A0, kh, lane, wm);
            ldbW(bA, st + O_WA, kh, lane, wn);
            mma2(acc, a0, bA);
            uint32_t a1[4], bc[4];
            ldaW(a1, st + O_A1, kh, lane, wm);
            ldbW(bc, CW0 + c*2048, kh, lane, wn);
            mma2(acc, a1, bc);
        }
    }

    // Epilogue + fused decout partial dot (exact tanhf — feeds output directly).
    #pragma unroll
    for (int h = 0; h < 2; ++h) {
        const int row = bm0 + wm*16 + (lane >> 2) + h*8;
        float s = 0.0f;
        #pragma unroll
        for (int ni = 0; ni < 2; ++ni) {
            const int col = bn0 + wn*16 + ni*8 + (lane & 3)*2;
            float v0 = acc[ni][h*2 + 0] + g_bs[3][col];
            float v1 = acc[ni][h*2 + 1] + g_bs[3][col+1];
            v0 = tanhf(v0); v1 = tanhf(v1);
            *(__half2*)(Cout + (size_t)row*H_ + col) =
                __halves2half2(__float2half(v0), __float2half(v1));
            s += v0*Wlin[col] + v1*Wlin[col+1];
        }
        s += __shfl_xor_sync(0xffffffffu, s, 1);
        s += __shfl_xor_sync(0xffffffffu, s, 2);
        if ((lane & 3) == 0)
            atomicAdd(&out[row*T_ + t], s);
    }
}

// ---------------------------------------------------------------------------
// Persistent whole-network kernel. 128 CTAs x 256 threads, 1 CTA/SM.
// ---------------------------------------------------------------------------
__global__ __launch_bounds__(256) void k_persist(
    const float* __restrict__ x,
    const float* __restrict__ eWih0,
    const float* __restrict__ dWih0,
    const float* __restrict__ dWlin, const float* __restrict__ dblin,
    float* __restrict__ out)
{
    extern __shared__ __half sm[];
    const int tid = threadIdx.x;
    const int bid = blockIdx.x;
    const int bn0 = (bid & 31) * BN;
    const int bm0 = (bid >> 5) * BM;
    const int grp = bid >> 5;
    const int lane = tid & 31, wrp = tid >> 5, wm = wrp >> 1, wn = wrp & 1;
    unsigned nb = 0;

    // Cache W0 (eWhh0) slice for the encoder phase.
    loadWc(g_W[0], sm + CW0_OFF, bn0, tid);

    // t=0: ys0[0] = tanh(x[0]@Wih0 + b) — epilogue only (Y = 0).
    {
        float z[2][4] = {};
        epi<1>(z, x, S_*I_, eWih0, g_bs[0], g_y0 /*slot 0*/, bm0, bn0, lane, wm, wn);
    }
    gb_arrive(tid, grp);
    preW5<2>(g_W[1], g_W[2], bn0, tid, sm);
    gb_wait(tid, grp, GSZ * (++nb));

    // ---- Fused encoder: t = 1..255 (enc0[t] + enc1[t-1]) ----
    for (int t = 1; t < S_; ++t) {
        const __half* Y  = g_y0 + (size_t)((t-1)&3)*BH;
        const __half* Hp = (t >= 2) ? g_h1 + (size_t)((t-2)&3)*BH : g_zb;
        enc_step<1>(t, Y, Hp, x, eWih0,
                    g_y0 + (size_t)(t&3)*BH, g_h1 + (size_t)((t-1)&3)*BH,
                    bm0, bn0, tid, sm);
        gb_arrive(tid, grp);
        preW5<2>(g_W[1], g_W[2], bn0, tid, sm);
        gb_wait(tid, grp, GSZ * (++nb));
    }
    // t = 256: enc1[255] only.
    enc_step<0>(S_, g_y0 + (size_t)((S_-1)&3)*BH, g_h1 + (size_t)((S_-2)&3)*BH,
                x, eWih0, g_y0, g_h1 + (size_t)((S_-1)&3)*BH, bm0, bn0, tid, sm);

    // Swap CW0 cache to W5 (dWhh1); prefetch W3 stream for dec0.
    gb_arrive(tid, grp);
    loadWc(g_W[5], sm + CW0_OFF, bn0, tid);
    preW5<1>(g_W[3], nullptr, bn0, tid, sm);
    gb_wait(tid, grp, GSZ * (++nb));

    // ---- Decoder: 2 counting-barrier intervals per step ----
    const __half* pA = g_y0 + (size_t)((S_-1)&3)*BH;   // h_enc0
    const __half* pB = g_h1 + (size_t)((S_-1)&3)*BH;   // h_enc1
    for (int t = 0; t < T_; ++t) {
        __half* nA = g_hA + (size_t)(t&1)*BH;
        const float* inp_prev = g_inp + (size_t)((t-1)&1)*B_*I_;
        float* inp_cur = g_inp + (size_t)(t&1)*B_*I_;
        if (t == 0)
            dec0<0>(pA, dWih0, inp_prev, inp_cur, out, t, dblin, nA, bm0, bn0, tid, sm);
        else
            dec0<1>(pA, dWih0, inp_prev, inp_cur, out, t, dblin, nA, bm0, bn0, tid, sm);
        gb_arrive(tid, grp);
        preW5<1>(g_W[4], nullptr, bn0, tid, sm);
        gb_wait(tid, grp, GSZ * (++nb));

        __half* nB = g_hB + (size_t)(t&1)*BH;
        dec1(nA, pB, dWlin, out, t, nB, bm0, bn0, tid, sm);
        gb_arrive(tid, grp);
        if (t + 1 < T_) preW5<1>(g_W[3], nullptr, bn0, tid, sm);
        gb_wait(tid, grp, GSZ * (++nb));

        pA = nA; pB = nB;
    }
}

// ---------------------------------------------------------------------------
// Orchestration: 3 launches on default stream (graph-capturable).
// ---------------------------------------------------------------------------
extern "C" void kernel_launch(void* const* d_in, const int* in_sizes, int n_in,
                              void* d_out, int out_size)
{
    (void)in_sizes; (void)n_in; (void)out_size;
    const float* x     = (const float*)d_in[0];
    const float* eWih0 = (const float*)d_in[2];
    const float* eWhh0 = (const float*)d_in[3];
    const float* ebih0 = (const float*)d_in[4];
    const float* ebhh0 = (const float*)d_in[5];
    const float* eWih1 = (const float*)d_in[6];
    const float* eWhh1 = (const float*)d_in[7];
    const float* ebih1 = (const float*)d_in[8];
    const float* ebhh1 = (const float*)d_in[9];
    const float* dWih0 = (const float*)d_in[10];
    const float* dWhh0 = (const float*)d_in[11];
    const float* dbih0 = (const float*)d_in[12];
    const float* dbhh0 = (const float*)d_in[13];
    const float* dWih1 = (const float*)d_in[14];
    const float* dWhh1 = (const float*)d_in[15];
    const float* dbih1 = (const float*)d_in[16];
    const float* dbhh1 = (const float*)d_in[17];
    const float* dWlin = (const float*)d_in[18];
    const float* dblin = (const float*)d_in[19];
    float* out = (float*)d_out;

    static bool s_attr = false;
    if (!s_attr) {
        cudaFuncSetAttribute(k_persist,
                             cudaFuncAttributeMaxDynamicSharedMemorySize, SMEM_BYTES);
        s_attr = true;
    }

    k_init<<<(BH + 255)/256, 256>>>(x, ebih0, ebhh0, ebih1, ebhh1,
                                    dbih0, dbhh0, dbih1, dbhh1);
    // order: eWhh0, eWih1, eWhh1, dWhh0, dWih1, dWhh1
    k_conv6<<<dim3(H_*H_/256, 6), 256>>>(eWhh0, eWih1, eWhh1, dWhh0, dWih1, dWhh1);
    k_persist<<<NCTA, THREADS, SMEM_BYTES>>>(x, eWih0, dWih0, dWlin, dblin, out);
}

// round 15
// speedup vs baseline: 1.2725x; 1.0578x over previous
#include <cuda_runtime.h>
#include <cuda_fp16.h>
#include <stdint.h>
#include <math.h>

// Problem dims (fixed)
#define B_ 256
#define S_ 256
#define I_ 3
#define H_ 1024
#define T_ 64
#define BH (B_*H_)

#define BM 64
#define BN 32
#define BK 64
#define KCH 16
#define NCTA 128
#define THREADS 256
#define GSZ 32            // CTAs per band

// Shared memory layout (halves):
//  [0, 32768)        : cached W slice A (CW0: eWhh0 / dWhh1)   64 KB
//  [32768, 65536)    : cached W slice B (CW2: eWhh1)            64 KB
//  [65536, +4*SSTR)  : 4 pipeline stages (A0 8KB, A1 8KB, WS 4KB)
//  Reduction scratch reuses the (dead) stage area between chunk loop and epilogue.
#define CW0_OFF 0
#define CW2_OFF 32768
#define STG_OFF 65536
#define O_A0 0
#define O_A1 4096
#define O_WS 8192
#define SSTR 10240
#define SMEM_BYTES ((STG_OFF + 4*SSTR)*2)   // 212992 B

#define RSTR 36            // reduction row stride (floats), bank-stagger
#define RPROD (64*RSTR)    // 2304 floats per product

// ---------------------------------------------------------------------------
// Device scratch (no allocation allowed)
// ---------------------------------------------------------------------------
__device__ __half g_y0[4*BH];
__device__ __half g_h1[4*BH];
__device__ __half g_hA[2*BH], g_hB[2*BH];
__device__ __half g_zb[BH];
__device__ float  g_inp[2*B_*I_];        // feedback ping-pong
// 0:eWhh0 1:eWih1 2:eWhh1 3:dWhh0 4:dWih1 5:dWhh1
__device__ __half g_W[6][H_*H_];
__device__ float  g_bs[4][H_];           // summed biases: enc0, enc1, dec0, dec1
__device__ unsigned g_cnt[4*32];         // per-band counters, padded

// ---------------------------------------------------------------------------
__global__ void k_init(const float* __restrict__ x,
                       const float* __restrict__ ebih0, const float* __restrict__ ebhh0,
                       const float* __restrict__ ebih1, const float* __restrict__ ebhh1,
                       const float* __restrict__ dbih0, const float* __restrict__ dbhh0,
                       const float* __restrict__ dbih1, const float* __restrict__ dbhh1) {
    int i = blockIdx.x * blockDim.x + threadIdx.x;
    if (i < 4) g_cnt[i*32] = 0;
    if (i < BH) g_zb[i] = __float2half(0.0f);
    if (i < B_*I_) {
        int b = i / I_, c = i % I_;
        g_inp[B_*I_ + i] = x[b*(S_*I_) + (S_-1)*I_ + c];   // slot 1 = initial
    }
    if (i < H_) {
        g_bs[0][i] = ebih0[i] + ebhh0[i];
        g_bs[1][i] = ebih1[i] + ebhh1[i];
        g_bs[2][i] = dbih0[i] + dbhh0[i];
        g_bs[3][i] = dbih1[i] + dbhh1[i];
    }
}

__global__ void k_conv6(const float* __restrict__ s0, const float* __restrict__ s1,
                        const float* __restrict__ s2, const float* __restrict__ s3,
                        const float* __restrict__ s4, const float* __restrict__ s5) {
    int i = blockIdx.x * blockDim.x + threadIdx.x;
    const float* srcs[6] = {s0, s1, s2, s3, s4, s5};
    int j = blockIdx.y;
    g_W[j][i] = __float2half(srcs[j][i]);
}

// ---------------------------------------------------------------------------
// Per-band (32-CTA) split barrier: monotonic counter, arrive early/wait late.
// ---------------------------------------------------------------------------
__device__ __forceinline__ void gb_arrive(int tid, int grp) {
    __syncthreads();
    if (tid == 0) { __threadfence(); atomicAdd(&g_cnt[grp*32], 1u); }
}
__device__ __forceinline__ void gb_wait(int tid, int grp, unsigned target) {
    if (tid == 0) {
        while (*(volatile unsigned*)&g_cnt[grp*32] < target) { }
        __threadfence();
    }
    __syncthreads();
}

__device__ __forceinline__ uint32_t smaddr(const void* p) {
    return (uint32_t)__cvta_generic_to_shared(p);
}
#define CP16(dst_sm, src_gm) \
    asm volatile("cp.async.cg.shared.global [%0], [%1], 16;\n" \
                 :: "r"(dst_sm), "l"(src_gm))
#define CPCOMMIT() asm volatile("cp.async.commit_group;")
#define CPWAIT2()  asm volatile("cp.async.wait_group 2;")

__device__ __forceinline__ float tanhA(float x) {
    float y; asm("tanh.approx.f32 %0, %1;" : "=f"(y) : "f"(x)); return y;
}

// Load this CTA's 32x1024 W slice into a smem cache region (16 chunks).
__device__ void loadWc(const __half* __restrict__ W, __half* Wc, int bn0, int tid) {
    const int lrow = tid >> 3, lcolh = (tid & 7) * 8;   // lrow 0..31
    const int sc = lcolh ^ ((lrow & 7) * 8);
    for (int kc = 0; kc < KCH; ++kc)
        CP16(smaddr(Wc + kc*2048 + lrow*64 + sc),
             W + (size_t)(bn0 + lrow)*H_ + kc*64 + lcolh);
    CPCOMMIT();
    asm volatile("cp.async.wait_group 0;");
    __syncthreads();
}

// Pre-barrier W-stream prefetch: chunks 0..2 into stages 0..2 (3 groups).
__device__ void preW3(const __half* __restrict__ Wst, int bn0, int tid, __half* sm) {
    __half* stg = sm + STG_OFF;
    const int lrow = tid >> 3, lcolh = (tid & 7) * 8;
    const int sc = lcolh ^ ((lrow & 7) * 8);
    #pragma unroll
    for (int c = 0; c < 3; ++c) {
        CP16(smaddr(stg + c*SSTR + O_WS + lrow*64 + sc),
             Wst + (size_t)(bn0 + lrow)*H_ + c*BK + lcolh);
        CPCOMMIT();
    }
}

// ldmatrix helpers (row width 64 halves, XOR swizzle on 8-half granule)
__device__ __forceinline__ void ldaW(uint32_t a[4], const __half* base, int kh, int lane, int wm) {
    int r  = wm*16 + (lane & 15);
    int cc = (kh + ((lane >> 4) * 8)) ^ ((r & 7) * 8);
    uint32_t addr = smaddr(base + r*64 + cc);
    asm volatile("ldmatrix.sync.aligned.m8n8.x4.shared.b16 {%0,%1,%2,%3}, [%4];"
        : "=r"(a[0]), "=r"(a[1]), "=r"(a[2]), "=r"(a[3]) : "r"(addr));
}
__device__ __forceinline__ void ldbW(uint32_t b[4], const __half* base, int kh, int lane, int wn) {
    int j  = lane >> 3;
    int r  = wn*16 + ((j >> 1) * 8) + (lane & 7);
    int cc = (kh + (j & 1) * 8) ^ ((r & 7) * 8);
    uint32_t addr = smaddr(base + r*64 + cc);
    asm volatile("ldmatrix.sync.aligned.m8n8.x4.shared.b16 {%0,%1,%2,%3}, [%4];"
        : "=r"(b[0]), "=r"(b[1]), "=r"(b[2]), "=r"(b[3]) : "r"(addr));
}
__device__ __forceinline__ void mma2(float acc[2][4], const uint32_t a[4], const uint32_t b[4]) {
    #pragma unroll
    for (int ni = 0; ni < 2; ++ni)
        asm volatile(
            "mma.sync.aligned.m16n8k16.row.col.f32.f16.f16.f32 "
            "{%0,%1,%2,%3}, {%4,%5,%6,%7}, {%8,%9}, {%0,%1,%2,%3};"
            : "+f"(acc[ni][0]), "+f"(acc[ni][1]), "+f"(acc[ni][2]), "+f"(acc[ni][3])
            : "r"(a[0]), "r"(a[1]), "r"(a[2]), "r"(a[3]),
              "r"(b[2*ni]), "r"(b[2*ni+1]));
}

// ---------------------------------------------------------------------------
// K-split reduction: 4 ordered add-passes into smem scratch R (stage area).
// acc layout per warp: [mi][wn][ni][4]; warp = (wm2, ks).
// ---------------------------------------------------------------------------
template<int NPROD>
__device__ __forceinline__ void kreduce(float* R,
    float a0[2][2][2][4], float a1[2][2][2][4],
    int wm2, int ks, int lane)
{
    #pragma unroll
    for (int pass = 0; pass < 4; ++pass) {
        __syncthreads();
        if (ks == pass) {
            #pragma unroll
            for (int mi = 0; mi < 2; ++mi)
            #pragma unroll
            for (int h = 0; h < 2; ++h) {
                const int row = wm2*32 + mi*16 + (lane >> 2) + h*8;
                #pragma unroll
                for (int wn = 0; wn < 2; ++wn)
                #pragma unroll
                for (int ni = 0; ni < 2; ++ni) {
                    const int col = wn*16 + ni*8 + (lane & 3)*2;
                    float* p = R + row*RSTR + col;
                    const float v0 = a0[mi][wn][ni][h*2+0];
                    const float v1 = a0[mi][wn][ni][h*2+1];
                    if (pass == 0) { p[0] = v0; p[1] = v1; }
                    else           { p[0] += v0; p[1] += v1; }
                    if (NPROD == 2) {
                        float* q = p + RPROD;
                        const float w0 = a1[mi][wn][ni][h*2+0];
                        const float w1 = a1[mi][wn][ni][h*2+1];
                        if (pass == 0) { q[0] = w0; q[1] = w1; }
                        else           { q[0] += w0; q[1] += w1; }
                    }
                }
            }
        }
    }
    __syncthreads();
}

// ---------------------------------------------------------------------------
// Fused encoder interval t (entry: W1 chunks 0..2 pre-issued into stages 0..2):
//   ENC0: ys0[t]  = tanh(x[t]@Wih0 + Y@W0cached + b)        (acc0)
//   always: h1[.] = tanh(Y@W1stream + H@W2cached + b)       (acc1)
// Warps: 2(m-half) x 4(k-split); warp tile 32m x 32n x one k16 per chunk.
// ---------------------------------------------------------------------------
template<int ENC0>
__device__ void enc_step(int t,
    const __half* __restrict__ Y, const __half* __restrict__ Hp,
    const float* __restrict__ x, const float* __restrict__ eWih0,
    __half* __restrict__ Yout, __half* __restrict__ Hout,
    int bm0, int bn0, int tid, __half* sm)
{
    const int lane = tid & 31, wrp = tid >> 5;
    const int wm2 = wrp >> 2, ks = wrp & 3;
    const int kh = ks * 16;
    const int lrow = tid >> 3, lcolh = (tid & 7) * 8;
    __half* stg = sm + STG_OFF;
    const __half* CW0 = sm + CW0_OFF;
    const __half* CW2 = sm + CW2_OFF;

    auto pfA = [&](int c, int slot) {
        __half* st = stg + slot*SSTR;
        const int k0 = c*BK;
        #pragma unroll
        for (int i = 0; i < 2; ++i) {
            int r  = lrow + 32*i;
            int sc = lcolh ^ ((r & 7) * 8);
            CP16(smaddr(st + O_A0 + r*64 + sc), Y  + (size_t)(bm0 + r)*H_ + k0 + lcolh);
            CP16(smaddr(st + O_A1 + r*64 + sc), Hp + (size_t)(bm0 + r)*H_ + k0 + lcolh);
        }
    };
    auto pfW = [&](int c, int slot) {
        __half* st = stg + slot*SSTR;
        const int k0 = c*BK;
        int sc = lcolh ^ ((lrow & 7) * 8);
        CP16(smaddr(st + O_WS + lrow*64 + sc), g_W[1] + (size_t)(bn0 + lrow)*H_ + k0 + lcolh);
    };

    pfA(0, 0); CPCOMMIT();
    pfA(1, 1); CPCOMMIT();
    pfA(2, 2); CPCOMMIT();

    float acc0[2][2][2][4] = {};
    float acc1[2][2][2][4] = {};
    for (int c = 0; c < KCH; ++c) {
        CPWAIT2();
        __syncthreads();
        if (c + 3 < KCH) { pfW(c + 3, (c + 3) & 3); pfA(c + 3, (c + 3) & 3); }
        CPCOMMIT();

        const __half* st = stg + (c & 3)*SSTR;
        uint32_t ay[2][4], ah[2][4];
        ldaW(ay[0], st + O_A0, kh, lane, wm2*2 + 0);
        ldaW(ay[1], st + O_A0, kh, lane, wm2*2 + 1);
        ldaW(ah[0], st + O_A1, kh, lane, wm2*2 + 0);
        ldaW(ah[1], st + O_A1, kh, lane, wm2*2 + 1);
        #pragma unroll
        for (int wn = 0; wn < 2; ++wn) {
            uint32_t b[4];
            if (ENC0) {
                ldbW(b, CW0 + c*2048, kh, lane, wn);
                mma2(acc0[0][wn], ay[0], b);
                mma2(acc0[1][wn], ay[1], b);
            }
            ldbW(b, st + O_WS, kh, lane, wn);
            mma2(acc1[0][wn], ay[0], b);
            mma2(acc1[1][wn], ay[1], b);
            ldbW(b, CW2 + c*2048, kh, lane, wn);
            mma2(acc1[0][wn], ah[0], b);
            mma2(acc1[1][wn], ah[1], b);
        }
    }

    // K-split reduction into stage-area scratch.
    float* R = reinterpret_cast<float*>(stg);
    if (ENC0) kreduce<2>(R, acc0, acc1, wm2, ks, lane);
    else      kreduce<1>(R, acc1, acc1, wm2, ks, lane);

    // Thread-linear epilogue: 1 row x 8 cols per thread.
    {
        const int mloc = tid >> 2, nloc = (tid & 3) * 8;
        const int row = bm0 + mloc, col0 = bn0 + nloc;
        __align__(16) __half hv[8];
        if (ENC0) {
            const float* xr = x + t*I_ + (size_t)row*(S_*I_);
            const float x0 = xr[0], x1 = xr[1], x2 = xr[2];
            const float4 f0 = *(const float4*)(R + mloc*RSTR + nloc);
            const float4 f1 = *(const float4*)(R + mloc*RSTR + nloc + 4);
            const float v[8] = {f0.x,f0.y,f0.z,f0.w,f1.x,f1.y,f1.z,f1.w};
            #pragma unroll
            for (int j = 0; j < 8; ++j) {
                const int col = col0 + j;
                float u = v[j] + x0*eWih0[col*3+0] + x1*eWih0[col*3+1] + x2*eWih0[col*3+2]
                        + g_bs[0][col];
                hv[j] = __float2half(tanhA(u));
            }
            *(float4*)(Yout + (size_t)row*H_ + col0) = *(float4*)hv;
        }
        const float* R1 = R + (ENC0 ? RPROD : 0);
        const float4 g0 = *(const float4*)(R1 + mloc*RSTR + nloc);
        const float4 g1 = *(const float4*)(R1 + mloc*RSTR + nloc + 4);
        const float w[8] = {g0.x,g0.y,g0.z,g0.w,g1.x,g1.y,g1.z,g1.w};
        #pragma unroll
        for (int j = 0; j < 8; ++j)
            hv[j] = __float2half(tanhA(w[j] + g_bs[1][col0 + j]));
        *(float4*)(Hout + (size_t)row*H_ + col0) = *(float4*)hv;
    }
    __syncthreads();   // R (stage area) dead before caller's prefetches
}

// ---------------------------------------------------------------------------
// Decoder layer-0 interval (W3=dWhh0 streamed; entry: W3 chunks 0..2 staged):
//   hA = tanh(A0@W3 + inp@dWih0 + b); inp computed on the fly from out[:,t-1].
// ---------------------------------------------------------------------------
template<int FB>
__device__ void dec0(
    const __half* __restrict__ A0,
    const float* __restrict__ dWih0,
    const float* __restrict__ inp_prev, float* __restrict__ inp_cur,
    float* __restrict__ out, int t, const float* __restrict__ dblin,
    __half* __restrict__ Cout,
    int bm0, int bn0, int tid, __half* sm)
{
    const int lane = tid & 31, wrp = tid >> 5;
    const int wm2 = wrp >> 2, ks = wrp & 3;
    const int kh = ks * 16;
    const int lrow = tid >> 3, lcolh = (tid & 7) * 8;
    __half* stg = sm + STG_OFF;

    auto pfA = [&](int c, int slot) {
        __half* st = stg + slot*SSTR;
        const int k0 = c*BK;
        #pragma unroll
        for (int i = 0; i < 2; ++i) {
            int r  = lrow + 32*i;
            int sc = lcolh ^ ((r & 7) * 8);
            CP16(smaddr(st + O_A0 + r*64 + sc), A0 + (size_t)(bm0 + r)*H_ + k0 + lcolh);
        }
    };
    auto pfW = [&](int c, int slot) {
        __half* st = stg + slot*SSTR;
        const int k0 = c*BK;
        int sc = lcolh ^ ((lrow & 7) * 8);
        CP16(smaddr(st + O_WS + lrow*64 + sc), g_W[3] + (size_t)(bn0 + lrow)*H_ + k0 + lcolh);
    };

    pfA(0, 0); CPCOMMIT();
    pfA(1, 1); CPCOMMIT();
    pfA(2, 2); CPCOMMIT();

    float acc[2][2][2][4] = {};
    for (int c = 0; c < KCH; ++c) {
        CPWAIT2();
        __syncthreads();
        if (c + 3 < KCH) { pfW(c + 3, (c + 3) & 3); pfA(c + 3, (c + 3) & 3); }
        CPCOMMIT();

        const __half* st = stg + (c & 3)*SSTR;
        uint32_t a0[2][4];
        ldaW(a0[0], st + O_A0, kh, lane, wm2*2 + 0);
        ldaW(a0[1], st + O_A0, kh, lane, wm2*2 + 1);
        #pragma unroll
        for (int wn = 0; wn < 2; ++wn) {
            uint32_t b[4];
            ldbW(b, st + O_WS, kh, lane, wn);
            mma2(acc[0][wn], a0[0], b);
            mma2(acc[1][wn], a0[1], b);
        }
    }

    float* R = reinterpret_cast<float*>(stg);
    kreduce<1>(R, acc, acc, wm2, ks, lane);

    // Thread-linear epilogue with on-the-fly feedback.
    {
        const int mloc = tid >> 2, nloc = (tid & 3) * 8;
        const int row = bm0 + mloc, col0 = bn0 + nloc;
        float c0, c1, c2;
        if (FB) {
            c0 = out[row*T_ + (t-1)];
            const float i0 = inp_prev[row*3 + 0];
            const float i1 = inp_prev[row*3 + 1];
            c1 = i0 - c0;
            c2 = i1 - c1;
        } else {
            c0 = inp_prev[row*3 + 0];
            c1 = inp_prev[row*3 + 1];
            c2 = inp_prev[row*3 + 2];
        }
        const float4 f0 = *(const float4*)(R + mloc*RSTR + nloc);
        const float4 f1 = *(const float4*)(R + mloc*RSTR + nloc + 4);
        const float v[8] = {f0.x,f0.y,f0.z,f0.w,f1.x,f1.y,f1.z,f1.w};
        __align__(16) __half hv[8];
        #pragma unroll
        for (int j = 0; j < 8; ++j) {
            const int col = col0 + j;
            float u = v[j] + c0*dWih0[col*3+0] + c1*dWih0[col*3+1] + c2*dWih0[col*3+2]
                    + g_bs[2][col];
            hv[j] = __float2half(tanhA(u));
        }
        *(float4*)(Cout + (size_t)row*H_ + col0) = *(float4*)hv;
        if (bn0 == 0 && (tid & 3) == 0) {
            inp_cur[row*3 + 0] = c0;
            inp_cur[row*3 + 1] = c1;
            inp_cur[row*3 + 2] = c2;
            out[row*T_ + t] = dblin[0];   // init for dec1's atomic partial dots
        }
    }
    __syncthreads();
}

// ---------------------------------------------------------------------------
// Decoder layer-1 interval (W4=dWih1 streamed, W5=dWhh1 cached in CW0):
//   hB = tanh(A0@W4 + A1@W5c + b); fused decout: atomicAdd partial hB.Wlin.
// ---------------------------------------------------------------------------
__device__ void dec1(
    const __half* __restrict__ A0, const __half* __restrict__ A1,
    const float* __restrict__ Wlin,
    float* __restrict__ out, int t,
    __half* __restrict__ Cout,
    int bm0, int bn0, int tid, __half* sm)
{
    const int lane = tid & 31, wrp = tid >> 5;
    const int wm2 = wrp >> 2, ks = wrp & 3;
    const int kh = ks * 16;
    const int lrow = tid >> 3, lcolh = (tid & 7) * 8;
    __half* stg = sm + STG_OFF;
    const __half* CW0 = sm + CW0_OFF;

    auto pfA = [&](int c, int slot) {
        __half* st = stg + slot*SSTR;
        const int k0 = c*BK;
        #pragma unroll
        for (int i = 0; i < 2; ++i) {
            int r  = lrow + 32*i;
            int sc = lcolh ^ ((r & 7) * 8);
            CP16(smaddr(st + O_A0 + r*64 + sc), A0 + (size_t)(bm0 + r)*H_ + k0 + lcolh);
            CP16(smaddr(st + O_A1 + r*64 + sc), A1 + (size_t)(bm0 + r)*H_ + k0 + lcolh);
        }
    };
    auto pfW = [&](int c, int slot) {
        __half* st = stg + slot*SSTR;
        const int k0 = c*BK;
        int sc = lcolh ^ ((lrow & 7) * 8);
        CP16(smaddr(st + O_WS + lrow*64 + sc), g_W[4] + (size_t)(bn0 + lrow)*H_ + k0 + lcolh);
    };

    pfA(0, 0); CPCOMMIT();
    pfA(1, 1); CPCOMMIT();
    pfA(2, 2); CPCOMMIT();

    float acc[2][2][2][4] = {};
    for (int c = 0; c < KCH; ++c) {
        CPWAIT2();
        __syncthreads();
        if (c + 3 < KCH) { pfW(c + 3, (c + 3) & 3); pfA(c + 3, (c + 3) & 3); }
        CPCOMMIT();

        const __half* st = stg + (c & 3)*SSTR;
        uint32_t a0[2][4], a1[2][4];
        ldaW(a0[0], st + O_A0, kh, lane, wm2*2 + 0);
        ldaW(a0[1], st + O_A0, kh, lane, wm2*2 + 1);
        ldaW(a1[0], st + O_A1, kh, lane, wm2*2 + 0);
        ldaW(a1[1], st + O_A1, kh, lane, wm2*2 + 1);
        #pragma unroll
        for (int wn = 0; wn < 2; ++wn) {
            uint32_t b[4];
            ldbW(b, st + O_WS, kh, lane, wn);
            mma2(acc[0][wn], a0[0], b);
            mma2(acc[1][wn], a0[1], b);
            ldbW(b, CW0 + c*2048, kh, lane, wn);
            mma2(acc[0][wn], a1[0], b);
            mma2(acc[1][wn], a1[1], b);
        }
    }

    float* R = reinterpret_cast<float*>(stg);
    kreduce<1>(R, acc, acc, wm2, ks, lane);

    // Thread-linear epilogue + fused decout partial dot (exact tanhf).
    {
        const int mloc = tid >> 2, nloc = (tid & 3) * 8;
        const int row = bm0 + mloc, col0 = bn0 + nloc;
        const float4 f0 = *(const float4*)(R + mloc*RSTR + nloc);
        const float4 f1 = *(const float4*)(R + mloc*RSTR + nloc + 4);
        const float v[8] = {f0.x,f0.y,f0.z,f0.w,f1.x,f1.y,f1.z,f1.w};
        __align__(16) __half hv[8];
        float s = 0.0f;
        #pragma unroll
        for (int j = 0; j < 8; ++j) {
            const int col = col0 + j;
            const float u = tanhf(v[j] + g_bs[3][col]);
            hv[j] = __float2half(u);
            s += u * Wlin[col];
        }
        *(float4*)(Cout + (size_t)row*H_ + col0) = *(float4*)hv;
        s += __shfl_xor_sync(0xffffffffu, s, 1);
        s += __shfl_xor_sync(0xffffffffu, s, 2);
        if ((lane & 3) == 0)
            atomicAdd(&out[row*T_ + t], s);
    }
    __syncthreads();
}

// ---------------------------------------------------------------------------
// Persistent whole-network kernel. 128 CTAs x 256 threads, 1 CTA/SM.
// ---------------------------------------------------------------------------
__global__ __launch_bounds__(256) void k_persist(
    const float* __restrict__ x,
    const float* __restrict__ eWih0,
    const float* __restrict__ dWih0,
    const float* __restrict__ dWlin, const float* __restrict__ dblin,
    float* __restrict__ out)
{
    extern __shared__ __half sm[];
    const int tid = threadIdx.x;
    const int bid = blockIdx.x;
    const int bn0 = (bid & 31) * BN;
    const int bm0 = (bid >> 5) * BM;
    const int grp = bid >> 5;
    unsigned nb = 0;

    // Cache W0 (eWhh0) and W2 (eWhh1) slices for the encoder phase.
    loadWc(g_W[0], sm + CW0_OFF, bn0, tid);
    loadWc(g_W[2], sm + CW2_OFF, bn0, tid);

    // t=0: ys0[0] = tanh(x[0]@Wih0 + b) — thread-linear epilogue only (Y = 0).
    {
        const int mloc = tid >> 2, nloc = (tid & 3) * 8;
        const int row = bm0 + mloc, col0 = bn0 + nloc;
        const float* xr = x + (size_t)row*(S_*I_);
        const float x0 = xr[0], x1 = xr[1], x2 = xr[2];
        __align__(16) __half hv[8];
        #pragma unroll
        for (int j = 0; j < 8; ++j) {
            const int col = col0 + j;
            float u = x0*eWih0[col*3+0] + x1*eWih0[col*3+1] + x2*eWih0[col*3+2]
                    + g_bs[0][col];
            hv[j] = __float2half(tanhA(u));
        }
        *(float4*)(g_y0 + (size_t)row*H_ + col0) = *(float4*)hv;
    }
    gb_arrive(tid, grp);
    preW3(g_W[1], bn0, tid, sm);
    gb_wait(tid, grp, GSZ * (++nb));

    // ---- Fused encoder: t = 1..255 (enc0[t] + enc1[t-1]) ----
    for (int t = 1; t < S_; ++t) {
        const __half* Y  = g_y0 + (size_t)((t-1)&3)*BH;
        const __half* Hp = (t >= 2) ? g_h1 + (size_t)((t-2)&3)*BH : g_zb;
        enc_step<1>(t, Y, Hp, x, eWih0,
                    g_y0 + (size_t)(t&3)*BH, g_h1 + (size_t)((t-1)&3)*BH,
                    bm0, bn0, tid, sm);
        gb_arrive(tid, grp);
        preW3(g_W[1], bn0, tid, sm);
        gb_wait(tid, grp, GSZ * (++nb));
    }
    // t = 256: enc1[255] only.
    enc_step<0>(S_, g_y0 + (size_t)((S_-1)&3)*BH, g_h1 + (size_t)((S_-2)&3)*BH,
                x, eWih0, g_y0, g_h1 + (size_t)((S_-1)&3)*BH, bm0, bn0, tid, sm);

    // Swap CW0 cache to W5 (dWhh1); prefetch W3 stream for dec0.
    gb_arrive(tid, grp);
    loadWc(g_W[5], sm + CW0_OFF, bn0, tid);
    preW3(g_W[3], bn0, tid, sm);
    gb_wait(tid, grp, GSZ * (++nb));

    // ---- Decoder: 2 counting-barrier intervals per step ----
    const __half* pA = g_y0 + (size_t)((S_-1)&3)*BH;   // h_enc0
    const __half* pB = g_h1 + (size_t)((S_-1)&3)*BH;   // h_enc1
    for (int t = 0; t < T_; ++t) {
        __half* nA = g_hA + (size_t)(t&1)*BH;
        const float* inp_prev = g_inp + (size_t)((t-1)&1)*B_*I_;
        float* inp_cur = g_inp + (size_t)(t&1)*B_*I_;
        if (t == 0)
            dec0<0>(pA, dWih0, inp_prev, inp_cur, out, t, dblin, nA, bm0, bn0, tid, sm);
        else
            dec0<1>(pA, dWih0, inp_prev, inp_cur, out, t, dblin, nA, bm0, bn0, tid, sm);
        gb_arrive(tid, grp);
        preW3(g_W[4], bn0, tid, sm);
        gb_wait(tid, grp, GSZ * (++nb));

        __half* nB = g_hB + (size_t)(t&1)*BH;
        dec1(nA, pB, dWlin, out, t, nB, bm0, bn0, tid, sm);
        gb_arrive(tid, grp);
        if (t + 1 < T_) preW3(g_W[3], bn0, tid, sm);
        gb_wait(tid, grp, GSZ * (++nb));

        pA = nA; pB = nB;
    }
}

// ---------------------------------------------------------------------------
// Orchestration: 3 launches on default stream (graph-capturable).
// ---------------------------------------------------------------------------
extern "C" void kernel_launch(void* const* d_in, const int* in_sizes, int n_in,
                              void* d_out, int out_size)
{
    (void)in_sizes; (void)n_in; (void)out_size;
    const float* x     = (const float*)d_in[0];
    const float* eWih0 = (const float*)d_in[2];
    const float* eWhh0 = (const float*)d_in[3];
    const float* ebih0 = (const float*)d_in[4];
    const float* ebhh0 = (const float*)d_in[5];
    const float* eWih1 = (const float*)d_in[6];
    const float* eWhh1 = (const float*)d_in[7];
    const float* ebih1 = (const float*)d_in[8];
    const float* ebhh1 = (const float*)d_in[9];
    const float* dWih0 = (const float*)d_in[10];
    const float* dWhh0 = (const float*)d_in[11];
    const float* dbih0 = (const float*)d_in[12];
    const float* dbhh0 = (const float*)d_in[13];
    const float* dWih1 = (const float*)d_in[14];
    const float* dWhh1 = (const float*)d_in[15];
    const float* dbih1 = (const float*)d_in[16];
    const float* dbhh1 = (const float*)d_in[17];
    const float* dWlin = (const float*)d_in[18];
    const float* dblin = (const float*)d_in[19];
    float* out = (float*)d_out;

    static bool s_attr = false;
    if (!s_attr) {
        cudaFuncSetAttribute(k_persist,
                             cudaFuncAttributeMaxDynamicSharedMemorySize, SMEM_BYTES);
        s_attr = true;
    }

    k_init<<<(BH + 255)/256, 256>>>(x, ebih0, ebhh0, ebih1, ebhh1,
                                    dbih0, dbhh0, dbih1, dbhh1);
    // order: eWhh0, eWih1, eWhh1, dWhh0, dWih1, dWhh1
    k_conv6<<<dim3(H_*H_/256, 6), 256>>>(eWhh0, eWih1, eWhh1, dWhh0, dWih1, dWhh1);
    k_persist<<<NCTA, THREADS, SMEM_BYTES>>>(x, eWih0, dWih0, dWlin, dblin, out);
}

// round 16
// speedup vs baseline: 1.3393x; 1.0525x over previous
#include <cuda_runtime.h>
#include <cuda_fp16.h>
#include <stdint.h>
#include <math.h>

// Problem dims (fixed)
#define B_ 256
#define S_ 256
#define I_ 3
#define H_ 1024
#define T_ 64
#define BH (B_*H_)

#define BM 64
#define BN 32
#define BK 64
#define KCH 16
#define NCTA 128
#define THREADS 256
#define GSZ 32            // CTAs per band

// Shared memory layout (halves):
//  [0, 32768)        : cached W slice A (CW0: eWhh0 / dWhh1)   64 KB
//  [32768, 65536)    : cached W slice B (CW2: eWhh1 / dWhh0)   64 KB
//  [65536, +4*SSTR)  : 4 pipeline stages (A0 8KB, A1 8KB, WS 4KB)
//  K-split scratch reuses the (dead) stage area between mainloop and epilogue.
#define CW0_OFF 0
#define CW2_OFF 32768
#define STG_OFF 65536
#define O_A0 0
#define O_A1 4096
#define O_WS 8192
#define SSTR 10240
#define SMEM_BYTES ((STG_OFF + 4*SSTR)*2)   // 212992 B

#define RSTR 36            // scratch row stride (floats)
#define RREG (64*RSTR)     // 2304 floats per (product, ks) region

// ---------------------------------------------------------------------------
// Device scratch (no allocation allowed)
// ---------------------------------------------------------------------------
__device__ __half g_y0[4*BH];
__device__ __half g_h1[4*BH];
__device__ __half g_hA[2*BH], g_hB[2*BH];
__device__ __half g_zb[BH];
__device__ float  g_inp[2*B_*I_];        // feedback ping-pong
// 0:eWhh0 1:eWih1 2:eWhh1 3:dWhh0 4:dWih1 5:dWhh1
__device__ __half g_W[6][H_*H_];
__device__ float  g_bs[4][H_];           // summed biases: enc0, enc1, dec0, dec1
__device__ unsigned g_cnt[4*32];         // per-band counters, padded

// ---------------------------------------------------------------------------
__global__ void k_init(const float* __restrict__ x,
                       const float* __restrict__ ebih0, const float* __restrict__ ebhh0,
                       const float* __restrict__ ebih1, const float* __restrict__ ebhh1,
                       const float* __restrict__ dbih0, const float* __restrict__ dbhh0,
                       const float* __restrict__ dbih1, const float* __restrict__ dbhh1) {
    int i = blockIdx.x * blockDim.x + threadIdx.x;
    if (i < 4) g_cnt[i*32] = 0;
    if (i < BH) g_zb[i] = __float2half(0.0f);
    if (i < B_*I_) {
        int b = i / I_, c = i % I_;
        g_inp[B_*I_ + i] = x[b*(S_*I_) + (S_-1)*I_ + c];   // slot 1 = initial
    }
    if (i < H_) {
        g_bs[0][i] = ebih0[i] + ebhh0[i];
        g_bs[1][i] = ebih1[i] + ebhh1[i];
        g_bs[2][i] = dbih0[i] + dbhh0[i];
        g_bs[3][i] = dbih1[i] + dbhh1[i];
    }
}

__global__ void k_conv6(const float* __restrict__ s0, const float* __restrict__ s1,
                        const float* __restrict__ s2, const float* __restrict__ s3,
                        const float* __restrict__ s4, const float* __restrict__ s5) {
    int i = blockIdx.x * blockDim.x + threadIdx.x;
    const float* srcs[6] = {s0, s1, s2, s3, s4, s5};
    int j = blockIdx.y;
    g_W[j][i] = __float2half(srcs[j][i]);
}

// ---------------------------------------------------------------------------
// Per-band (32-CTA) split barrier: monotonic counter, arrive early/wait late.
// ---------------------------------------------------------------------------
__device__ __forceinline__ void gb_arrive(int tid, int grp) {
    __syncthreads();
    if (tid == 0) { __threadfence(); atomicAdd(&g_cnt[grp*32], 1u); }
}
__device__ __forceinline__ void gb_wait(int tid, int grp, unsigned target) {
    if (tid == 0) {
        while (*(volatile unsigned*)&g_cnt[grp*32] < target) { }
        __threadfence();
    }
    __syncthreads();
}

__device__ __forceinline__ uint32_t smaddr(const void* p) {
    return (uint32_t)__cvta_generic_to_shared(p);
}
#define CP16(dst_sm, src_gm) \
    asm volatile("cp.async.cg.shared.global [%0], [%1], 16;\n" \
                 :: "r"(dst_sm), "l"(src_gm))
#define CPCOMMIT() asm volatile("cp.async.commit_group;")
#define CPWAIT2()  asm volatile("cp.async.wait_group 2;")

__device__ __forceinline__ float tanhA(float x) {
    float y; asm("tanh.approx.f32 %0, %1;" : "=f"(y) : "f"(x)); return y;
}

// Load this CTA's 32x1024 W slice into a smem cache region (16 chunks).
__device__ void loadWc(const __half* __restrict__ W, __half* Wc, int bn0, int tid) {
    const int lrow = tid >> 3, lcolh = (tid & 7) * 8;   // lrow 0..31
    const int sc = lcolh ^ ((lrow & 7) * 8);
    for (int kc = 0; kc < KCH; ++kc)
        CP16(smaddr(Wc + kc*2048 + lrow*64 + sc),
             W + (size_t)(bn0 + lrow)*H_ + kc*64 + lcolh);
    CPCOMMIT();
    asm volatile("cp.async.wait_group 0;");
    __syncthreads();
}

// Pre-barrier W-stream prefetch: chunks 0..2 into stages 0..2 (3 groups).
__device__ void preW3(const __half* __restrict__ Wst, int bn0, int tid, __half* sm) {
    __half* stg = sm + STG_OFF;
    const int lrow = tid >> 3, lcolh = (tid & 7) * 8;
    const int sc = lcolh ^ ((lrow & 7) * 8);
    #pragma unroll
    for (int c = 0; c < 3; ++c) {
        CP16(smaddr(stg + c*SSTR + O_WS + lrow*64 + sc),
             Wst + (size_t)(bn0 + lrow)*H_ + c*BK + lcolh);
        CPCOMMIT();
    }
}

// ldmatrix helpers (row width 64 halves, XOR swizzle on 8-half granule)
__device__ __forceinline__ void ldaW(uint32_t a[4], const __half* base, int kh, int lane, int wm) {
    int r  = wm*16 + (lane & 15);
    int cc = (kh + ((lane >> 4) * 8)) ^ ((r & 7) * 8);
    uint32_t addr = smaddr(base + r*64 + cc);
    asm volatile("ldmatrix.sync.aligned.m8n8.x4.shared.b16 {%0,%1,%2,%3}, [%4];"
        : "=r"(a[0]), "=r"(a[1]), "=r"(a[2]), "=r"(a[3]) : "r"(addr));
}
__device__ __forceinline__ void ldbW(uint32_t b[4], const __half* base, int kh, int lane, int wn) {
    int j  = lane >> 3;
    int r  = wn*16 + ((j >> 1) * 8) + (lane & 7);
    int cc = (kh + (j & 1) * 8) ^ ((r & 7) * 8);
    uint32_t addr = smaddr(base + r*64 + cc);
    asm volatile("ldmatrix.sync.aligned.m8n8.x4.shared.b16 {%0,%1,%2,%3}, [%4];"
        : "=r"(b[0]), "=r"(b[1]), "=r"(b[2]), "=r"(b[3]) : "r"(addr));
}
__device__ __forceinline__ void mma2(float acc[2][4], const uint32_t a[4], const uint32_t b[4]) {
    #pragma unroll
    for (int ni = 0; ni < 2; ++ni)
        asm volatile(
            "mma.sync.aligned.m16n8k16.row.col.f32.f16.f16.f32 "
            "{%0,%1,%2,%3}, {%4,%5,%6,%7}, {%8,%9}, {%0,%1,%2,%3};"
            : "+f"(acc[ni][0]), "+f"(acc[ni][1]), "+f"(acc[ni][2]), "+f"(acc[ni][3])
            : "r"(a[0]), "r"(a[1]), "r"(a[2]), "r"(a[3]),
              "r"(b[2*ni]), "r"(b[2*ni+1]));
}

// ---------------------------------------------------------------------------
// Parallel k-split store: each warp writes its partials to its own region
// (product p, split ks). Caller syncs once before/after.
// ---------------------------------------------------------------------------
__device__ __forceinline__ void kstore(float* R, int p, float a[2][2][2][4],
                                       int wm2, int ks, int lane) {
    float* Rp = R + (p*4 + ks)*RREG;
    #pragma unroll
    for (int mi = 0; mi < 2; ++mi)
    #pragma unroll
    for (int h = 0; h < 2; ++h) {
        const int row = wm2*32 + mi*16 + (lane >> 2) + h*8;
        #pragma unroll
        for (int wn = 0; wn < 2; ++wn)
        #pragma unroll
        for (int ni = 0; ni < 2; ++ni) {
            const int col = wn*16 + ni*8 + (lane & 3)*2;
            *(float2*)(Rp + row*RSTR + col) =
                make_float2(a[mi][wn][ni][h*2+0], a[mi][wn][ni][h*2+1]);
        }
    }
}
// Sum 4 k-split regions for product p at this thread's (mloc, nloc).
__device__ __forceinline__ void ksum(const float* R, int p, int mloc, int nloc, float v[8]) {
    #pragma unroll
    for (int j = 0; j < 8; ++j) v[j] = 0.0f;
    #pragma unroll
    for (int ks = 0; ks < 4; ++ks) {
        const float* Rp = R + (p*4 + ks)*RREG + mloc*RSTR + nloc;
        const float4 f0 = *(const float4*)(Rp);
        const float4 f1 = *(const float4*)(Rp + 4);
        v[0]+=f0.x; v[1]+=f0.y; v[2]+=f0.z; v[3]+=f0.w;
        v[4]+=f1.x; v[5]+=f1.y; v[6]+=f1.z; v[7]+=f1.w;
    }
}

// ---------------------------------------------------------------------------
// Fused encoder interval t (entry: W1 chunks 0..2 pre-issued into stages 0..2):
//   ENC0: ys0[t]  = tanh(x[t]@Wih0 + Y@W0cached + b)        (acc0)
//   always: h1[.] = tanh(Y@W1stream + H@W2cached + b)       (acc1)
// Warps: 2(m-half) x 4(k-split); warp tile 32m x 32n x one k16 per chunk.
// ---------------------------------------------------------------------------
template<int ENC0>
__device__ void enc_step(int t,
    const __half* __restrict__ Y, const __half* __restrict__ Hp,
    const float* __restrict__ x, const float* __restrict__ eWih0,
    __half* __restrict__ Yout, __half* __restrict__ Hout,
    int bm0, int bn0, int tid, __half* sm)
{
    const int lane = tid & 31, wrp = tid >> 5;
    const int wm2 = wrp >> 2, ks = wrp & 3;
    const int kh = ks * 16;
    const int lrow = tid >> 3, lcolh = (tid & 7) * 8;
    __half* stg = sm + STG_OFF;
    const __half* CW0 = sm + CW0_OFF;
    const __half* CW2 = sm + CW2_OFF;

    auto pfA = [&](int c, int slot) {
        __half* st = stg + slot*SSTR;
        const int k0 = c*BK;
        #pragma unroll
        for (int i = 0; i < 2; ++i) {
            int r  = lrow + 32*i;
            int sc = lcolh ^ ((r & 7) * 8);
            CP16(smaddr(st + O_A0 + r*64 + sc), Y  + (size_t)(bm0 + r)*H_ + k0 + lcolh);
            CP16(smaddr(st + O_A1 + r*64 + sc), Hp + (size_t)(bm0 + r)*H_ + k0 + lcolh);
        }
    };
    auto pfW = [&](int c, int slot) {
        __half* st = stg + slot*SSTR;
        const int k0 = c*BK;
        int sc = lcolh ^ ((lrow & 7) * 8);
        CP16(smaddr(st + O_WS + lrow*64 + sc), g_W[1] + (size_t)(bn0 + lrow)*H_ + k0 + lcolh);
    };

    pfA(0, 0); CPCOMMIT();
    pfA(1, 1); CPCOMMIT();
    pfA(2, 2); CPCOMMIT();

    float acc0[2][2][2][4] = {};
    float acc1[2][2][2][4] = {};
    for (int c = 0; c < KCH; ++c) {
        CPWAIT2();
        __syncthreads();
        if (c + 3 < KCH) { pfW(c + 3, (c + 3) & 3); pfA(c + 3, (c + 3) & 3); }
        CPCOMMIT();

        const __half* st = stg + (c & 3)*SSTR;
        uint32_t ay[2][4], ah[2][4];
        ldaW(ay[0], st + O_A0, kh, lane, wm2*2 + 0);
        ldaW(ay[1], st + O_A0, kh, lane, wm2*2 + 1);
        ldaW(ah[0], st + O_A1, kh, lane, wm2*2 + 0);
        ldaW(ah[1], st + O_A1, kh, lane, wm2*2 + 1);
        #pragma unroll
        for (int wn = 0; wn < 2; ++wn) {
            uint32_t b[4];
            if (ENC0) {
                ldbW(b, CW0 + c*2048, kh, lane, wn);
                mma2(acc0[0][wn], ay[0], b);
                mma2(acc0[1][wn], ay[1], b);
            }
            ldbW(b, st + O_WS, kh, lane, wn);
            mma2(acc1[0][wn], ay[0], b);
            mma2(acc1[1][wn], ay[1], b);
            ldbW(b, CW2 + c*2048, kh, lane, wn);
            mma2(acc1[0][wn], ah[0], b);
            mma2(acc1[1][wn], ah[1], b);
        }
    }

    // Parallel k-split store into stage-area scratch (single sync each side).
    float* R = reinterpret_cast<float*>(stg);
    __syncthreads();
    if (ENC0) { kstore(R, 0, acc0, wm2, ks, lane); kstore(R, 1, acc1, wm2, ks, lane); }
    else      { kstore(R, 0, acc1, wm2, ks, lane); }
    __syncthreads();

    // Thread-linear epilogue: 1 row x 8 cols per thread.
    {
        const int mloc = tid >> 2, nloc = (tid & 3) * 8;
        const int row = bm0 + mloc, col0 = bn0 + nloc;
        __align__(16) __half hv[8];
        float v[8];
        if (ENC0) {
            const float* xr = x + t*I_ + (size_t)row*(S_*I_);
            const float x0 = xr[0], x1 = xr[1], x2 = xr[2];
            ksum(R, 0, mloc, nloc, v);
            #pragma unroll
            for (int j = 0; j < 8; ++j) {
                const int col = col0 + j;
                float u = v[j] + x0*eWih0[col*3+0] + x1*eWih0[col*3+1] + x2*eWih0[col*3+2]
                        + g_bs[0][col];
                hv[j] = __float2half(tanhA(u));
            }
            *(float4*)(Yout + (size_t)row*H_ + col0) = *(float4*)hv;
        }
        ksum(R, ENC0 ? 1 : 0, mloc, nloc, v);
        #pragma unroll
        for (int j = 0; j < 8; ++j)
            hv[j] = __float2half(tanhA(v[j] + g_bs[1][col0 + j]));
        *(float4*)(Hout + (size_t)row*H_ + col0) = *(float4*)hv;
    }
    __syncthreads();   // R (stage area) dead before caller's prefetches
}

// ---------------------------------------------------------------------------
// Decoder layer-0 interval (W3=dWhh0 CACHED in CW2; A-only stream):
//   hA = tanh(A0@W3c + inp@dWih0 + b); inp computed on the fly from out[:,t-1].
// ---------------------------------------------------------------------------
template<int FB>
__device__ void dec0(
    const __half* __restrict__ A0,
    const float* __restrict__ dWih0,
    const float* __restrict__ inp_prev, float* __restrict__ inp_cur,
    float* __restrict__ out, int t, const float* __restrict__ dblin,
    __half* __restrict__ Cout,
    int bm0, int bn0, int tid, __half* sm)
{
    const int lane = tid & 31, wrp = tid >> 5;
    const int wm2 = wrp >> 2, ks = wrp & 3;
    const int kh = ks * 16;
    const int lrow = tid >> 3, lcolh = (tid & 7) * 8;
    __half* stg = sm + STG_OFF;
    const __half* CW2 = sm + CW2_OFF;

    auto pfA = [&](int c, int slot) {
        __half* st = stg + slot*SSTR;
        const int k0 = c*BK;
        #pragma unroll
        for (int i = 0; i < 2; ++i) {
            int r  = lrow + 32*i;
            int sc = lcolh ^ ((r & 7) * 8);
            CP16(smaddr(st + O_A0 + r*64 + sc), A0 + (size_t)(bm0 + r)*H_ + k0 + lcolh);
        }
    };

    pfA(0, 0); CPCOMMIT();
    pfA(1, 1); CPCOMMIT();
    pfA(2, 2); CPCOMMIT();

    float acc[2][2][2][4] = {};
    for (int c = 0; c < KCH; ++c) {
        CPWAIT2();
        __syncthreads();
        if (c + 3 < KCH) pfA(c + 3, (c + 3) & 3);
        CPCOMMIT();

        const __half* st = stg + (c & 3)*SSTR;
        uint32_t a0[2][4];
        ldaW(a0[0], st + O_A0, kh, lane, wm2*2 + 0);
        ldaW(a0[1], st + O_A0, kh, lane, wm2*2 + 1);
        #pragma unroll
        for (int wn = 0; wn < 2; ++wn) {
            uint32_t b[4];
            ldbW(b, CW2 + c*2048, kh, lane, wn);
            mma2(acc[0][wn], a0[0], b);
            mma2(acc[1][wn], a0[1], b);
        }
    }

    float* R = reinterpret_cast<float*>(stg);
    __syncthreads();
    kstore(R, 0, acc, wm2, ks, lane);
    __syncthreads();

    // Thread-linear epilogue with on-the-fly feedback.
    {
        const int mloc = tid >> 2, nloc = (tid & 3) * 8;
        const int row = bm0 + mloc, col0 = bn0 + nloc;
        float c0, c1, c2;
        if (FB) {
            c0 = out[row*T_ + (t-1)];
            const float i0 = inp_prev[row*3 + 0];
            const float i1 = inp_prev[row*3 + 1];
            c1 = i0 - c0;
            c2 = i1 - c1;
        } else {
            c0 = inp_prev[row*3 + 0];
            c1 = inp_prev[row*3 + 1];
            c2 = inp_prev[row*3 + 2];
        }
        float v[8];
        ksum(R, 0, mloc, nloc, v);
        __align__(16) __half hv[8];
        #pragma unroll
        for (int j = 0; j < 8; ++j) {
            const int col = col0 + j;
            float u = v[j] + c0*dWih0[col*3+0] + c1*dWih0[col*3+1] + c2*dWih0[col*3+2]
                    + g_bs[2][col];
            hv[j] = __float2half(tanhA(u));
        }
        *(float4*)(Cout + (size_t)row*H_ + col0) = *(float4*)hv;
        if (bn0 == 0 && (tid & 3) == 0) {
            inp_cur[row*3 + 0] = c0;
            inp_cur[row*3 + 1] = c1;
            inp_cur[row*3 + 2] = c2;
            out[row*T_ + t] = dblin[0];   // init for dec1's atomic partial dots
        }
    }
    __syncthreads();
}

// ---------------------------------------------------------------------------
// Decoder layer-1 interval (W4=dWih1 streamed, W5=dWhh1 cached in CW0):
//   hB = tanh(A0@W4 + A1@W5c + b); fused decout: atomicAdd partial hB.Wlin.
// ---------------------------------------------------------------------------
__device__ void dec1(
    const __half* __restrict__ A0, const __half* __restrict__ A1,
    const float* __restrict__ Wlin,
    float* __restrict__ out, int t,
    __half* __restrict__ Cout,
    int bm0, int bn0, int tid, __half* sm)
{
    const int lane = tid & 31, wrp = tid >> 5;
    const int wm2 = wrp >> 2, ks = wrp & 3;
    const int kh = ks * 16;
    const int lrow = tid >> 3, lcolh = (tid & 7) * 8;
    __half* stg = sm + STG_OFF;
    const __half* CW0 = sm + CW0_OFF;

    auto pfA = [&](int c, int slot) {
        __half* st = stg + slot*SSTR;
        const int k0 = c*BK;
        #pragma unroll
        for (int i = 0; i < 2; ++i) {
            int r  = lrow + 32*i;
            int sc = lcolh ^ ((r & 7) * 8);
            CP16(smaddr(st + O_A0 + r*64 + sc), A0 + (size_t)(bm0 + r)*H_ + k0 + lcolh);
            CP16(smaddr(st + O_A1 + r*64 + sc), A1 + (size_t)(bm0 + r)*H_ + k0 + lcolh);
        }
    };
    auto pfW = [&](int c, int slot) {
        __half* st = stg + slot*SSTR;
        const int k0 = c*BK;
        int sc = lcolh ^ ((lrow & 7) * 8);
        CP16(smaddr(st + O_WS + lrow*64 + sc), g_W[4] + (size_t)(bn0 + lrow)*H_ + k0 + lcolh);
    };

    pfA(0, 0); CPCOMMIT();
    pfA(1, 1); CPCOMMIT();
    pfA(2, 2); CPCOMMIT();

    float acc[2][2][2][4] = {};
    for (int c = 0; c < KCH; ++c) {
        CPWAIT2();
        __syncthreads();
        if (c + 3 < KCH) { pfW(c + 3, (c + 3) & 3); pfA(c + 3, (c + 3) & 3); }
        CPCOMMIT();

        const __half* st = stg + (c & 3)*SSTR;
        uint32_t a0[2][4], a1[2][4];
        ldaW(a0[0], st + O_A0, kh, lane, wm2*2 + 0);
        ldaW(a0[1], st + O_A0, kh, lane, wm2*2 + 1);
        ldaW(a1[0], st + O_A1, kh, lane, wm2*2 + 0);
        ldaW(a1[1], st + O_A1, kh, lane, wm2*2 + 1);
        #pragma unroll
        for (int wn = 0; wn < 2; ++wn) {
            uint32_t b[4];
            ldbW(b, st + O_WS, kh, lane, wn);
            mma2(acc[0][wn], a0[0], b);
            mma2(acc[1][wn], a0[1], b);
            ldbW(b, CW0 + c*2048, kh, lane, wn);
            mma2(acc[0][wn], a1[0], b);
            mma2(acc[1][wn], a1[1], b);
        }
    }

    float* R = reinterpret_cast<float*>(stg);
    __syncthreads();
    kstore(R, 0, acc, wm2, ks, lane);
    __syncthreads();

    // Thread-linear epilogue + fused decout partial dot (exact tanhf).
    {
        const int mloc = tid >> 2, nloc = (tid & 3) * 8;
        const int row = bm0 + mloc, col0 = bn0 + nloc;
        float v[8];
        ksum(R, 0, mloc, nloc, v);
        __align__(16) __half hv[8];
        float s = 0.0f;
        #pragma unroll
        for (int j = 0; j < 8; ++j) {
            const int col = col0 + j;
            const float u = tanhf(v[j] + g_bs[3][col]);
            hv[j] = __float2half(u);
            s += u * Wlin[col];
        }
        *(float4*)(Cout + (size_t)row*H_ + col0) = *(float4*)hv;
        s += __shfl_xor_sync(0xffffffffu, s, 1);
        s += __shfl_xor_sync(0xffffffffu, s, 2);
        if ((lane & 3) == 0)
            atomicAdd(&out[row*T_ + t], s);
    }
    __syncthreads();
}

// ---------------------------------------------------------------------------
// Persistent whole-network kernel. 128 CTAs x 256 threads, 1 CTA/SM.
// ---------------------------------------------------------------------------
__global__ __launch_bounds__(256) void k_persist(
    const float* __restrict__ x,
    const float* __restrict__ eWih0,
    const float* __restrict__ dWih0,
    const float* __restrict__ dWlin, const float* __restrict__ dblin,
    float* __restrict__ out)
{
    extern __shared__ __half sm[];
    const int tid = threadIdx.x;
    const int bid = blockIdx.x;
    const int bn0 = (bid & 31) * BN;
    const int bm0 = (bid >> 5) * BM;
    const int grp = bid >> 5;
    unsigned nb = 0;

    // Cache W0 (eWhh0) and W2 (eWhh1) slices for the encoder phase.
    loadWc(g_W[0], sm + CW0_OFF, bn0, tid);
    loadWc(g_W[2], sm + CW2_OFF, bn0, tid);

    // t=0: ys0[0] = tanh(x[0]@Wih0 + b) — thread-linear epilogue only (Y = 0).
    {
        const int mloc = tid >> 2, nloc = (tid & 3) * 8;
        const int row = bm0 + mloc, col0 = bn0 + nloc;
        const float* xr = x + (size_t)row*(S_*I_);
        const float x0 = xr[0], x1 = xr[1], x2 = xr[2];
        __align__(16) __half hv[8];
        #pragma unroll
        for (int j = 0; j < 8; ++j) {
            const int col = col0 + j;
            float u = x0*eWih0[col*3+0] + x1*eWih0[col*3+1] + x2*eWih0[col*3+2]
                    + g_bs[0][col];
            hv[j] = __float2half(tanhA(u));
        }
        *(float4*)(g_y0 + (size_t)row*H_ + col0) = *(float4*)hv;
    }
    gb_arrive(tid, grp);
    preW3(g_W[1], bn0, tid, sm);
    gb_wait(tid, grp, GSZ * (++nb));

    // ---- Fused encoder: t = 1..255 (enc0[t] + enc1[t-1]) ----
    for (int t = 1; t < S_; ++t) {
        const __half* Y  = g_y0 + (size_t)((t-1)&3)*BH;
        const __half* Hp = (t >= 2) ? g_h1 + (size_t)((t-2)&3)*BH : g_zb;
        enc_step<1>(t, Y, Hp, x, eWih0,
                    g_y0 + (size_t)(t&3)*BH, g_h1 + (size_t)((t-1)&3)*BH,
                    bm0, bn0, tid, sm);
        gb_arrive(tid, grp);
        preW3(g_W[1], bn0, tid, sm);
        gb_wait(tid, grp, GSZ * (++nb));
    }
    // t = 256: enc1[255] only.
    enc_step<0>(S_, g_y0 + (size_t)((S_-1)&3)*BH, g_h1 + (size_t)((S_-2)&3)*BH,
                x, eWih0, g_y0, g_h1 + (size_t)((S_-1)&3)*BH, bm0, bn0, tid, sm);

    // Swap caches: CW0 <- W5 (dWhh1), CW2 <- W3 (dWhh0).
    gb_arrive(tid, grp);
    loadWc(g_W[5], sm + CW0_OFF, bn0, tid);
    loadWc(g_W[3], sm + CW2_OFF, bn0, tid);
    gb_wait(tid, grp, GSZ * (++nb));

    // ---- Decoder: 2 counting-barrier intervals per step ----
    const __half* pA = g_y0 + (size_t)((S_-1)&3)*BH;   // h_enc0
    const __half* pB = g_h1 + (size_t)((S_-1)&3)*BH;   // h_enc1
    for (int t = 0; t < T_; ++t) {
        __half* nA = g_hA + (size_t)(t&1)*BH;
        const float* inp_prev = g_inp + (size_t)((t-1)&1)*B_*I_;
        float* inp_cur = g_inp + (size_t)(t&1)*B_*I_;
        if (t == 0)
            dec0<0>(pA, dWih0, inp_prev, inp_cur, out, t, dblin, nA, bm0, bn0, tid, sm);
        else
            dec0<1>(pA, dWih0, inp_prev, inp_cur, out, t, dblin, nA, bm0, bn0, tid, sm);
        gb_arrive(tid, grp);
        preW3(g_W[4], bn0, tid, sm);     // stage W4 for dec1 in the wait window
        gb_wait(tid, grp, GSZ * (++nb));

        __half* nB = g_hB + (size_t)(t&1)*BH;
        dec1(nA, pB, dWlin, out, t, nB, bm0, bn0, tid, sm);
        gb_arrive(tid, grp);
        gb_wait(tid, grp, GSZ * (++nb));

        pA = nA; pB = nB;
    }
}

// ---------------------------------------------------------------------------
// Orchestration: 3 launches on default stream (graph-capturable).
// ---------------------------------------------------------------------------
extern "C" void kernel_launch(void* const* d_in, const int* in_sizes, int n_in,
                              void* d_out, int out_size)
{
    (void)in_sizes; (void)n_in; (void)out_size;
    const float* x     = (const float*)d_in[0];
    const float* eWih0 = (const float*)d_in[2];
    const float* eWhh0 = (const float*)d_in[3];
    const float* ebih0 = (const float*)d_in[4];
    const float* ebhh0 = (const float*)d_in[5];
    const float* eWih1 = (const float*)d_in[6];
    const float* eWhh1 = (const float*)d_in[7];
    const float* ebih1 = (const float*)d_in[8];
    const float* ebhh1 = (const float*)d_in[9];
    const float* dWih0 = (const float*)d_in[10];
    const float* dWhh0 = (const float*)d_in[11];
    const float* dbih0 = (const float*)d_in[12];
    const float* dbhh0 = (const float*)d_in[13];
    const float* dWih1 = (const float*)d_in[14];
    const float* dWhh1 = (const float*)d_in[15];
    const float* dbih1 = (const float*)d_in[16];
    const float* dbhh1 = (const float*)d_in[17];
    const float* dWlin = (const float*)d_in[18];
    const float* dblin = (const float*)d_in[19];
    float* out = (float*)d_out;

    static bool s_attr = false;
    if (!s_attr) {
        cudaFuncSetAttribute(k_persist,
                             cudaFuncAttributeMaxDynamicSharedMemorySize, SMEM_BYTES);
        s_attr = true;
    }

    k_init<<<(BH + 255)/256, 256>>>(x, ebih0, ebhh0, ebih1, ebhh1,
                                    dbih0, dbhh0, dbih1, dbhh1);
    // order: eWhh0, eWih1, eWhh1, dWhh0, dWih1, dWhh1
    k_conv6<<<dim3(H_*H_/256, 6), 256>>>(eWhh0, eWih1, eWhh1, dWhh0, dWih1, dWhh1);
    k_persist<<<NCTA, THREADS, SMEM_BYTES>>>(x, eWih0, dWih0, dWlin, dblin, out);
}